// round 2
// baseline (speedup 1.0000x reference)
#include <cuda_runtime.h>
#include <cuda_bf16.h>
#include <cstdint>

// ---------------------------------------------------------------------------
// MambaBlock: B=4, L=1024, D_MODEL=768, D_INNER=1536, D_STATE=16, DT_RANK=48
//  1) LN stats (per (b,l) over 768 channels)           -> g_stats
//  2) transpose + LN apply: (B,C,L) -> (B*L, C)        -> g_hn
//  3) GEMM1: hn @ W_in^T  (4096x3072x768)              -> g_xz
//  4) depthwise causal conv(4) + silu                  -> g_xssm
//  5) GEMM xproj: xssm @ W_xproj^T (4096x80x1536)      -> g_xdbl
//  6) GEMM dt: xdbl[:, :48] @ W_dt^T + b_dt, softplus  -> g_dt
//  7) selective scan (serial over L), + D*x, *silu(z)  -> g_y
//  8) GEMM out: y @ W_out^T, transpose-store + x       -> d_out
// ---------------------------------------------------------------------------

#define Bsz 4
#define Lsz 1024
#define DM  768
#define DI  1536
#define DS  16
#define DTR 48
#define MROWS (Bsz * Lsz)   // 4096

// scratch (device globals; allocation anywhere is forbidden)
__device__ float g_hn  [MROWS * DM];        // 12.6 MB
__device__ float g_xz  [MROWS * 2 * DI];    // 50.3 MB
__device__ float g_xssm[MROWS * DI];        // 25.2 MB
__device__ float g_xdbl[MROWS * 80];        //  1.3 MB
__device__ float g_dt  [MROWS * DI];        // 25.2 MB
__device__ float g_y   [MROWS * DI];        // 25.2 MB
__device__ float g_stats[MROWS * 2];        // mu, rstd

// ---------------------------------------------------------------------------
// 1) LayerNorm statistics. block: 256 threads = 64 l-values x 4 c-chunks.
// ---------------------------------------------------------------------------
__global__ void ln_stats_kernel(const float* __restrict__ x)
{
    __shared__ float s_sum[256];
    __shared__ float s_sq[256];
    int tid  = threadIdx.x;
    int lid  = tid & 63;           // l within chunk
    int part = tid >> 6;           // 0..3 -> c range
    int b    = blockIdx.y;
    int l    = blockIdx.x * 64 + lid;
    const float* xb = x + (size_t)b * DM * Lsz + l;

    float sum = 0.f, sq = 0.f;
    int c0 = part * (DM / 4);
    #pragma unroll 8
    for (int c = c0; c < c0 + DM / 4; c++) {
        float v = xb[(size_t)c * Lsz];
        sum += v;
        sq  += v * v;
    }
    s_sum[tid] = sum;
    s_sq[tid]  = sq;
    __syncthreads();
    if (part == 0) {
        float ts = s_sum[tid] + s_sum[tid + 64] + s_sum[tid + 128] + s_sum[tid + 192];
        float tq = s_sq[tid]  + s_sq[tid + 64]  + s_sq[tid + 128]  + s_sq[tid + 192];
        float mu = ts / DM;
        float var = tq / DM - mu * mu;
        float rstd = rsqrtf(var + 1e-5f);
        int bl = b * Lsz + l;
        g_stats[bl * 2 + 0] = mu;
        g_stats[bl * 2 + 1] = rstd;
    }
}

// ---------------------------------------------------------------------------
// 2) Transpose (B,C,L)->(B*L,C) with LN applied. 32x32 smem tile.
// block (32,8); grid (L/32, C/32, B).
// ---------------------------------------------------------------------------
__global__ void ln_apply_kernel(const float* __restrict__ x,
                                const float* __restrict__ gamma,
                                const float* __restrict__ beta)
{
    __shared__ float tile[32][33];
    int b  = blockIdx.z;
    int c0 = blockIdx.y * 32;
    int l0 = blockIdx.x * 32;
    const float* xb = x + (size_t)b * DM * Lsz;

    #pragma unroll
    for (int i0 = 0; i0 < 4; i0++) {
        int c = c0 + threadIdx.y + i0 * 8;
        tile[threadIdx.y + i0 * 8][threadIdx.x] = xb[(size_t)c * Lsz + l0 + threadIdx.x];
    }
    __syncthreads();
    #pragma unroll
    for (int i0 = 0; i0 < 4; i0++) {
        int l  = l0 + threadIdx.y + i0 * 8;
        int c  = c0 + threadIdx.x;
        int bl = b * Lsz + l;
        float mu   = g_stats[bl * 2 + 0];
        float rstd = g_stats[bl * 2 + 1];
        float v = tile[threadIdx.x][threadIdx.y + i0 * 8];
        g_hn[(size_t)bl * DM + c] = (v - mu) * rstd * gamma[c] + beta[c];
    }
}

// ---------------------------------------------------------------------------
// Generic tiled fp32 GEMM:  C[M,N] = A[M,K] * B[N,K]^T   (row-major "NT")
// BM=BN=128, BK=8, 256 threads, 8x8 per thread.
// EPI 0: plain store. EPI 1: softplus(acc + bias[n]). EPI 2: transpose + x.
// Requires K % 8 == 0, lda/ldb % 4 == 0.
// ---------------------------------------------------------------------------
template<int EPI>
__global__ void __launch_bounds__(256)
gemm_nt_kernel(const float* __restrict__ A, int lda,
               const float* __restrict__ B, int ldb,
               float* __restrict__ C, int ldc,
               int M, int N, int K,
               const float* __restrict__ bias,
               const float* __restrict__ xres)
{
    __shared__ float As[8][128];
    __shared__ float Bs[8][128];

    int tid = threadIdx.x;
    int tx = tid & 15;         // 0..15 -> n
    int ty = tid >> 4;         // 0..15 -> m
    int m0 = blockIdx.y * 128;
    int n0 = blockIdx.x * 128;

    int ldrow  = tid >> 1;         // 0..127
    int ldcol4 = (tid & 1) * 4;    // 0 or 4

    float acc[8][8];
    #pragma unroll
    for (int i = 0; i < 8; i++)
        #pragma unroll
        for (int j = 0; j < 8; j++) acc[i][j] = 0.f;

    for (int k0 = 0; k0 < K; k0 += 8) {
        // load A tile
        {
            int gm = m0 + ldrow;
            float4 v = make_float4(0.f, 0.f, 0.f, 0.f);
            if (gm < M)
                v = *reinterpret_cast<const float4*>(&A[(size_t)gm * lda + k0 + ldcol4]);
            As[ldcol4 + 0][ldrow] = v.x;
            As[ldcol4 + 1][ldrow] = v.y;
            As[ldcol4 + 2][ldrow] = v.z;
            As[ldcol4 + 3][ldrow] = v.w;
        }
        // load B tile
        {
            int gn = n0 + ldrow;
            float4 v = make_float4(0.f, 0.f, 0.f, 0.f);
            if (gn < N)
                v = *reinterpret_cast<const float4*>(&B[(size_t)gn * ldb + k0 + ldcol4]);
            Bs[ldcol4 + 0][ldrow] = v.x;
            Bs[ldcol4 + 1][ldrow] = v.y;
            Bs[ldcol4 + 2][ldrow] = v.z;
            Bs[ldcol4 + 3][ldrow] = v.w;
        }
        __syncthreads();

        #pragma unroll
        for (int k = 0; k < 8; k++) {
            float af[8], bf[8];
            *reinterpret_cast<float4*>(&af[0]) = *reinterpret_cast<const float4*>(&As[k][ty * 8]);
            *reinterpret_cast<float4*>(&af[4]) = *reinterpret_cast<const float4*>(&As[k][ty * 8 + 4]);
            *reinterpret_cast<float4*>(&bf[0]) = *reinterpret_cast<const float4*>(&Bs[k][tx * 8]);
            *reinterpret_cast<float4*>(&bf[4]) = *reinterpret_cast<const float4*>(&Bs[k][tx * 8 + 4]);
            #pragma unroll
            for (int i = 0; i < 8; i++)
                #pragma unroll
                for (int j = 0; j < 8; j++)
                    acc[i][j] += af[i] * bf[j];
        }
        __syncthreads();
    }

    #pragma unroll
    for (int i = 0; i < 8; i++) {
        int gm = m0 + ty * 8 + i;
        if (gm >= M) continue;
        #pragma unroll
        for (int j = 0; j < 8; j++) {
            int gn = n0 + tx * 8 + j;
            if (gn >= N) continue;
            float v = acc[i][j];
            if (EPI == 1) {
                v += bias[gn];
                v = (v > 20.f) ? v : log1pf(expf(v));
                C[(size_t)gm * ldc + gn] = v;
            } else if (EPI == 2) {
                int b = gm >> 10;       // /1024
                int l = gm & 1023;
                size_t oi = ((size_t)(b * DM + gn)) * Lsz + l;
                C[oi] = v + xres[oi];
            } else {
                C[(size_t)gm * ldc + gn] = v;
            }
        }
    }
}

// ---------------------------------------------------------------------------
// 4) depthwise causal conv(4) + bias + silu.  idx over (bl, d).
// ---------------------------------------------------------------------------
__global__ void conv_silu_kernel(const float* __restrict__ conv_w,
                                 const float* __restrict__ conv_b)
{
    int idx = blockIdx.x * blockDim.x + threadIdx.x;
    if (idx >= MROWS * DI) return;
    int d  = idx % DI;
    int bl = idx / DI;
    int l  = bl & (Lsz - 1);

    float acc = conv_b[d];
    #pragma unroll
    for (int j = 0; j < 4; j++) {
        int ll = l - 3 + j;
        if (ll >= 0)
            acc += conv_w[d * 4 + j] * g_xz[(size_t)(bl - 3 + j) * (2 * DI) + d];
    }
    // silu
    g_xssm[idx] = acc / (1.f + expf(-acc));
}

// ---------------------------------------------------------------------------
// 7) selective scan. 16 lanes per (b,d) pair; 2 pairs per warp.
// y[bl,d] = (sum_n h*C + D[d]*x) * silu(z)
// ---------------------------------------------------------------------------
__global__ void scan_kernel(const float* __restrict__ A_log,
                            const float* __restrict__ Dw)
{
    int gid = blockIdx.x * (blockDim.x >> 4) + (threadIdx.x >> 4);
    if (gid >= Bsz * DI) return;
    int lane = threadIdx.x & 15;
    int b = gid / DI;
    int d = gid % DI;

    float Aval = -expf(A_log[d * DS + lane]);
    float Dd   = Dw[d];
    float h = 0.f;

    const float* dtp = g_dt   + (size_t)b * Lsz * DI + d;
    const float* xp  = g_xssm + (size_t)b * Lsz * DI + d;
    const float* dbl = g_xdbl + (size_t)b * Lsz * 80;
    const float* zp  = g_xz   + (size_t)b * Lsz * (2 * DI) + DI + d;
    float*       yp  = g_y    + (size_t)b * Lsz * DI + d;

    for (int l = 0; l < Lsz; l++) {
        float dt_t = dtp[(size_t)l * DI];
        float x_t  = xp [(size_t)l * DI];
        float B_t  = dbl[l * 80 + DTR + lane];
        float C_t  = dbl[l * 80 + DTR + DS + lane];
        float dA = expf(dt_t * Aval);
        h = dA * h + (dt_t * x_t) * B_t;
        float part = h * C_t;
        part += __shfl_xor_sync(0xFFFFFFFFu, part, 8);
        part += __shfl_xor_sync(0xFFFFFFFFu, part, 4);
        part += __shfl_xor_sync(0xFFFFFFFFu, part, 2);
        part += __shfl_xor_sync(0xFFFFFFFFu, part, 1);
        if (lane == 0) {
            float z  = zp[(size_t)l * (2 * DI)];
            float sz = z / (1.f + expf(-z));
            yp[(size_t)l * DI] = (part + Dd * x_t) * sz;
        }
    }
}

// Device-global base pointers for GEMM arguments (resolved in device code).
// We wrap GEMM launches with tiny helper kernels?  No — simpler: pass the
// addresses via constant device pointers obtained with & in device lambdas is
// not possible from host.  Instead use dedicated wrapper kernels that forward
// to the template with global-symbol addresses.
__global__ void __launch_bounds__(256) gemm1_wrap()
{
    // not used
}

extern "C" void kernel_launch(void* const* d_in, const int* in_sizes, int n_in,
                              void* d_out, int out_size)
{
    const float* x      = (const float*)d_in[0];
    const float* gamma  = (const float*)d_in[1];
    const float* beta   = (const float*)d_in[2];
    const float* W_in   = (const float*)d_in[3];
    const float* conv_w = (const float*)d_in[4];
    const float* conv_b = (const float*)d_in[5];
    const float* W_xproj= (const float*)d_in[6];
    const float* W_dt   = (const float*)d_in[7];
    const float* b_dt   = (const float*)d_in[8];
    const float* A_log  = (const float*)d_in[9];
    const float* Dw     = (const float*)d_in[10];
    const float* W_out  = (const float*)d_in[11];
    float* out = (float*)d_out;

    // Device-global scratch addresses: obtained once per process via the
    // static-initializer-safe route (cudaGetSymbolAddress is not an
    // allocation).  To keep kernel_launch to pure kernel launches we resolve
    // them lazily into plain statics.
    static float *hn = nullptr, *xz = nullptr, *xssm = nullptr, *xdbl = nullptr,
                 *dtb = nullptr, *yb = nullptr;
    if (!hn) {
        cudaGetSymbolAddress((void**)&hn,   g_hn);
        cudaGetSymbolAddress((void**)&xz,   g_xz);
        cudaGetSymbolAddress((void**)&xssm, g_xssm);
        cudaGetSymbolAddress((void**)&xdbl, g_xdbl);
        cudaGetSymbolAddress((void**)&dtb,  g_dt);
        cudaGetSymbolAddress((void**)&yb,   g_y);
    }

    // 1) LN stats
    ln_stats_kernel<<<dim3(Lsz / 64, Bsz), 256>>>(x);
    // 2) transpose + LN apply
    ln_apply_kernel<<<dim3(Lsz / 32, DM / 32, Bsz), dim3(32, 8)>>>(x, gamma, beta);
    // 3) GEMM1: xz = hn @ W_in^T   (4096 x 3072 x 768)
    gemm_nt_kernel<0><<<dim3((2 * DI) / 128, MROWS / 128), 256>>>(
        hn, DM, W_in, DM, xz, 2 * DI, MROWS, 2 * DI, DM, nullptr, nullptr);
    // 4) conv + silu
    conv_silu_kernel<<<(MROWS * DI + 255) / 256, 256>>>(conv_w, conv_b);
    // 5) xproj: xdbl = xssm @ W_xproj^T   (4096 x 80 x 1536)
    gemm_nt_kernel<0><<<dim3(1, MROWS / 128), 256>>>(
        xssm, DI, W_xproj, DI, xdbl, 80, MROWS, 80, DI, nullptr, nullptr);
    // 6) dt = softplus(xdbl[:, :48] @ W_dt^T + b_dt)   (4096 x 1536 x 48)
    gemm_nt_kernel<1><<<dim3(DI / 128, MROWS / 128), 256>>>(
        xdbl, 80, W_dt, DTR, dtb, DI, MROWS, DI, DTR, b_dt, nullptr);
    // 7) scan
    scan_kernel<<<(Bsz * DI * 16 + 255) / 256, 256>>>(A_log, Dw);
    // 8) out = y @ W_out^T, transposed store + residual x   (4096 x 768 x 1536)
    gemm_nt_kernel<2><<<dim3(DM / 128, MROWS / 128), 256>>>(
        yb, DI, W_out, DI, out, 0, MROWS, DM, DI, nullptr, x);
}

// round 3
// speedup vs baseline: 1.4277x; 1.4277x over previous
#include <cuda_runtime.h>
#include <cuda_bf16.h>
#include <cstdint>

// ---------------------------------------------------------------------------
// MambaBlock: B=4, L=1024, D_MODEL=768, D_INNER=1536, D_STATE=16, DT_RANK=48
// All four GEMMs on tensor cores via mma.sync.m16n8k8.tf32.
// ---------------------------------------------------------------------------

#define Bsz 4
#define Lsz 1024
#define DM  768
#define DI  1536
#define DS  16
#define DTR 48
#define MROWS (Bsz * Lsz)   // 4096

// scratch (device globals; allocation anywhere is forbidden)
__device__ __align__(16) float g_hn  [MROWS * DM];
__device__ __align__(16) float g_xz  [MROWS * 2 * DI];
__device__ __align__(16) float g_xssm[MROWS * DI];
__device__ __align__(16) float g_xdbl[MROWS * 80];
__device__ __align__(16) float g_dt  [MROWS * DI];
__device__ __align__(16) float g_y   [MROWS * DI];
__device__ __align__(16) float g_stats[MROWS * 2];

// ---------------------------------------------------------------------------
// 1) LayerNorm statistics
// ---------------------------------------------------------------------------
__global__ void ln_stats_kernel(const float* __restrict__ x)
{
    __shared__ float s_sum[256];
    __shared__ float s_sq[256];
    int tid  = threadIdx.x;
    int lid  = tid & 63;
    int part = tid >> 6;
    int b    = blockIdx.y;
    int l    = blockIdx.x * 64 + lid;
    const float* xb = x + (size_t)b * DM * Lsz + l;

    float sum = 0.f, sq = 0.f;
    int c0 = part * (DM / 4);
    #pragma unroll 8
    for (int c = c0; c < c0 + DM / 4; c++) {
        float v = xb[(size_t)c * Lsz];
        sum += v;
        sq  += v * v;
    }
    s_sum[tid] = sum;
    s_sq[tid]  = sq;
    __syncthreads();
    if (part == 0) {
        float ts = s_sum[tid] + s_sum[tid + 64] + s_sum[tid + 128] + s_sum[tid + 192];
        float tq = s_sq[tid]  + s_sq[tid + 64]  + s_sq[tid + 128]  + s_sq[tid + 192];
        float mu = ts / DM;
        float var = tq / DM - mu * mu;
        float rstd = rsqrtf(var + 1e-5f);
        int bl = b * Lsz + l;
        g_stats[bl * 2 + 0] = mu;
        g_stats[bl * 2 + 1] = rstd;
    }
}

// ---------------------------------------------------------------------------
// 2) Transpose (B,C,L)->(B*L,C) with LN applied
// ---------------------------------------------------------------------------
__global__ void ln_apply_kernel(const float* __restrict__ x,
                                const float* __restrict__ gamma,
                                const float* __restrict__ beta)
{
    __shared__ float tile[32][33];
    int b  = blockIdx.z;
    int c0 = blockIdx.y * 32;
    int l0 = blockIdx.x * 32;
    const float* xb = x + (size_t)b * DM * Lsz;

    #pragma unroll
    for (int i0 = 0; i0 < 4; i0++) {
        int c = c0 + threadIdx.y + i0 * 8;
        tile[threadIdx.y + i0 * 8][threadIdx.x] = xb[(size_t)c * Lsz + l0 + threadIdx.x];
    }
    __syncthreads();
    #pragma unroll
    for (int i0 = 0; i0 < 4; i0++) {
        int l  = l0 + threadIdx.y + i0 * 8;
        int c  = c0 + threadIdx.x;
        int bl = b * Lsz + l;
        float mu   = g_stats[bl * 2 + 0];
        float rstd = g_stats[bl * 2 + 1];
        float v = tile[threadIdx.x][threadIdx.y + i0 * 8];
        g_hn[(size_t)bl * DM + c] = (v - mu) * rstd * gamma[c] + beta[c];
    }
}

// ---------------------------------------------------------------------------
// tf32 helpers
// ---------------------------------------------------------------------------
__device__ __forceinline__ uint32_t f2tf32(float f)
{
    uint32_t r;
    asm("cvt.rna.tf32.f32 %0, %1;" : "=r"(r) : "f"(f));
    return r;
}

__device__ __forceinline__ void mma_tf32(float* c, const uint32_t* a, const uint32_t* b)
{
    asm volatile(
        "mma.sync.aligned.m16n8k8.row.col.f32.tf32.tf32.f32 "
        "{%0,%1,%2,%3}, {%4,%5,%6,%7}, {%8,%9}, {%0,%1,%2,%3};"
        : "+f"(c[0]), "+f"(c[1]), "+f"(c[2]), "+f"(c[3])
        : "r"(a[0]), "r"(a[1]), "r"(a[2]), "r"(a[3]), "r"(b[0]), "r"(b[1]));
}

// ---------------------------------------------------------------------------
// Tensor-core GEMM:  C[M,N] = A[M,K] * B[N,K]^T  (both row-major)
// BM=128, BK=16, 256 threads, warp layout WARPS_M x WARPS_N.
// EPI 0: plain. EPI 1: softplus(acc + bias[n]). EPI 2: transpose store + xres.
// Requires: M % 128 == 0, N == gridDim.x * BN, K % 16 == 0, lda/ldb % 4 == 0.
// ---------------------------------------------------------------------------
template<int BN, int WARPS_M, int WARPS_N, int EPI>
__global__ void __launch_bounds__(256)
gemm_tf32(const float* __restrict__ A, int lda,
          const float* __restrict__ B, int ldb,
          float* __restrict__ C, int ldc,
          int K,
          const float* __restrict__ bias,
          const float* __restrict__ xres)
{
    constexpr int BM = 128;
    constexpr int WM = BM / WARPS_M;
    constexpr int WN = BN / WARPS_N;
    constexpr int MT = WM / 16;
    constexpr int NT = WN / 8;
    constexpr int LDT = 20;              // smem row stride (16 + 4 pad words)
    constexpr int NA4 = BM * 4;          // float4 loads per A stage (512)
    constexpr int NB4 = BN * 4;          // float4 loads per B stage

    __shared__ uint32_t As[2][BM * LDT];
    __shared__ uint32_t Bs[2][BN * LDT];

    const int tid   = threadIdx.x;
    const int warp  = tid >> 5;
    const int lane  = tid & 31;
    const int g     = lane >> 2;   // group 0..7
    const int t     = lane & 3;    // thread in group

    const int warp_m = warp / WARPS_N;
    const int warp_n = warp % WARPS_N;
    const int wm0 = warp_m * WM;
    const int wn0 = warp_n * WN;

    const int m0 = blockIdx.y * BM;
    const int n0 = blockIdx.x * BN;

    float acc[MT][NT][4];
    #pragma unroll
    for (int i = 0; i < MT; i++)
        #pragma unroll
        for (int j = 0; j < NT; j++)
            #pragma unroll
            for (int q = 0; q < 4; q++) acc[i][j][q] = 0.f;

    // loader indices (thread -> (row, kq))
    const int a_row = tid >> 2;          // 0..63 (+64 for 2nd)
    const int a_kq  = (tid & 3) * 4;

    const int niter = K / 16;

    float4 pa[2], pb[2];

    auto loadA = [&](int i, int k0) {
        return *reinterpret_cast<const float4*>(
            &A[(size_t)(m0 + a_row + 64 * i) * lda + k0 + a_kq]);
    };
    auto loadB = [&](int i, int k0) -> float4 {
        int idx = tid + 256 * i;
        if (idx < NB4) {
            int r  = idx >> 2;
            int kq = (idx & 3) * 4;
            return *reinterpret_cast<const float4*>(
                &B[(size_t)(n0 + r) * ldb + k0 + kq]);
        }
        return make_float4(0.f, 0.f, 0.f, 0.f);
    };
    auto stsA = [&](int s) {
        #pragma unroll
        for (int i = 0; i < NA4 / 256; i++) {
            int r = a_row + 64 * i;
            uint32_t* p = &As[s][r * LDT + a_kq];
            p[0] = f2tf32(pa[i].x); p[1] = f2tf32(pa[i].y);
            p[2] = f2tf32(pa[i].z); p[3] = f2tf32(pa[i].w);
        }
    };
    auto stsB = [&](int s) {
        #pragma unroll
        for (int i = 0; i < (NB4 + 255) / 256; i++) {
            int idx = tid + 256 * i;
            if (idx < NB4) {
                int r  = idx >> 2;
                int kq = (idx & 3) * 4;
                uint32_t* p = &Bs[s][r * LDT + kq];
                p[0] = f2tf32(pb[i].x); p[1] = f2tf32(pb[i].y);
                p[2] = f2tf32(pb[i].z); p[3] = f2tf32(pb[i].w);
            }
        }
    };

    // prefetch + stage 0
    #pragma unroll
    for (int i = 0; i < NA4 / 256; i++) pa[i] = loadA(i, 0);
    #pragma unroll
    for (int i = 0; i < (NB4 + 255) / 256; i++) pb[i] = loadB(i, 0);
    stsA(0); stsB(0);
    __syncthreads();

    int s = 0;
    for (int it = 0; it < niter; it++) {
        if (it + 1 < niter) {
            int k0 = (it + 1) * 16;
            #pragma unroll
            for (int i = 0; i < NA4 / 256; i++) pa[i] = loadA(i, k0);
            #pragma unroll
            for (int i = 0; i < (NB4 + 255) / 256; i++) pb[i] = loadB(i, k0);
        }

        const uint32_t* as = As[s];
        const uint32_t* bs = Bs[s];
        #pragma unroll
        for (int ks = 0; ks < 2; ks++) {
            const int kk = ks * 8;
            uint32_t afr[MT][4];
            uint32_t bfr[NT][2];
            #pragma unroll
            for (int i = 0; i < MT; i++) {
                int base = wm0 + 16 * i;
                afr[i][0] = as[(base + g)     * LDT + kk + t];
                afr[i][1] = as[(base + g + 8) * LDT + kk + t];
                afr[i][2] = as[(base + g)     * LDT + kk + t + 4];
                afr[i][3] = as[(base + g + 8) * LDT + kk + t + 4];
            }
            #pragma unroll
            for (int j = 0; j < NT; j++) {
                int bb = wn0 + 8 * j;
                bfr[j][0] = bs[(bb + g) * LDT + kk + t];
                bfr[j][1] = bs[(bb + g) * LDT + kk + t + 4];
            }
            #pragma unroll
            for (int i = 0; i < MT; i++)
                #pragma unroll
                for (int j = 0; j < NT; j++)
                    mma_tf32(acc[i][j], afr[i], bfr[j]);
        }

        if (it + 1 < niter) {
            stsA(s ^ 1); stsB(s ^ 1);
            __syncthreads();
            s ^= 1;
        }
    }

    // epilogue
    #pragma unroll
    for (int i = 0; i < MT; i++) {
        int r0 = m0 + wm0 + 16 * i + g;
        int r1 = r0 + 8;
        #pragma unroll
        for (int j = 0; j < NT; j++) {
            int col = n0 + wn0 + 8 * j + 2 * t;
            float c0 = acc[i][j][0], c1 = acc[i][j][1];
            float c2 = acc[i][j][2], c3 = acc[i][j][3];
            if (EPI == 1) {
                float b0 = bias[col], b1 = bias[col + 1];
                c0 += b0; c1 += b1; c2 += b0; c3 += b1;
                c0 = (c0 > 20.f) ? c0 : log1pf(expf(c0));
                c1 = (c1 > 20.f) ? c1 : log1pf(expf(c1));
                c2 = (c2 > 20.f) ? c2 : log1pf(expf(c2));
                c3 = (c3 > 20.f) ? c3 : log1pf(expf(c3));
            }
            if (EPI == 2) {
                int b0i = r0 >> 10, l0i = r0 & 1023;
                int b1i = r1 >> 10, l1i = r1 & 1023;
                size_t o00 = ((size_t)(b0i * DM + col))     * Lsz + l0i;
                size_t o01 = ((size_t)(b0i * DM + col + 1)) * Lsz + l0i;
                size_t o10 = ((size_t)(b1i * DM + col))     * Lsz + l1i;
                size_t o11 = ((size_t)(b1i * DM + col + 1)) * Lsz + l1i;
                C[o00] = c0 + xres[o00];
                C[o01] = c1 + xres[o01];
                C[o10] = c2 + xres[o10];
                C[o11] = c3 + xres[o11];
            } else {
                float2 v01 = make_float2(c0, c1);
                float2 v23 = make_float2(c2, c3);
                *reinterpret_cast<float2*>(&C[(size_t)r0 * ldc + col]) = v01;
                *reinterpret_cast<float2*>(&C[(size_t)r1 * ldc + col]) = v23;
            }
        }
    }
}

// ---------------------------------------------------------------------------
// 4) depthwise causal conv(4) + bias + silu
// ---------------------------------------------------------------------------
__global__ void conv_silu_kernel(const float* __restrict__ conv_w,
                                 const float* __restrict__ conv_b)
{
    int idx = blockIdx.x * blockDim.x + threadIdx.x;
    if (idx >= MROWS * DI) return;
    int d  = idx % DI;
    int bl = idx / DI;
    int l  = bl & (Lsz - 1);

    float acc = conv_b[d];
    #pragma unroll
    for (int j = 0; j < 4; j++) {
        int ll = l - 3 + j;
        if (ll >= 0)
            acc += conv_w[d * 4 + j] * g_xz[(size_t)(bl - 3 + j) * (2 * DI) + d];
    }
    g_xssm[idx] = acc / (1.f + expf(-acc));
}

// ---------------------------------------------------------------------------
// 7) selective scan: 4 lanes per (b,d), 4 states per lane.
// ---------------------------------------------------------------------------
__global__ void scan_kernel(const float* __restrict__ A_log,
                            const float* __restrict__ Dw)
{
    int pair = blockIdx.x * (blockDim.x >> 2) + (threadIdx.x >> 2);
    if (pair >= Bsz * DI) return;
    int ln = threadIdx.x & 3;
    int b = pair / DI;
    int d = pair % DI;
    int n0 = ln * 4;

    float Av[4], h[4];
    #pragma unroll
    for (int j = 0; j < 4; j++) {
        Av[j] = -expf(A_log[d * DS + n0 + j]);
        h[j] = 0.f;
    }
    float Dd = Dw[d];

    const float* dtp = g_dt   + (size_t)b * Lsz * DI + d;
    const float* xp  = g_xssm + (size_t)b * Lsz * DI + d;
    const float* dbl = g_xdbl + (size_t)b * Lsz * 80;
    const float* zp  = g_xz   + (size_t)b * Lsz * (2 * DI) + DI + d;
    float*       yp  = g_y    + (size_t)b * Lsz * DI + d;

    #pragma unroll 4
    for (int l = 0; l < Lsz; l++) {
        float dt_t = dtp[(size_t)l * DI];
        float x_t  = xp [(size_t)l * DI];
        float4 Bv = *reinterpret_cast<const float4*>(&dbl[l * 80 + DTR + n0]);
        float4 Cv = *reinterpret_cast<const float4*>(&dbl[l * 80 + DTR + DS + n0]);
        float dtx = dt_t * x_t;
        float part;
        h[0] = expf(dt_t * Av[0]) * h[0] + dtx * Bv.x;
        h[1] = expf(dt_t * Av[1]) * h[1] + dtx * Bv.y;
        h[2] = expf(dt_t * Av[2]) * h[2] + dtx * Bv.z;
        h[3] = expf(dt_t * Av[3]) * h[3] + dtx * Bv.w;
        part = h[0] * Cv.x + h[1] * Cv.y + h[2] * Cv.z + h[3] * Cv.w;
        part += __shfl_xor_sync(0xFFFFFFFFu, part, 2);
        part += __shfl_xor_sync(0xFFFFFFFFu, part, 1);
        if (ln == 0) {
            float z  = zp[(size_t)l * (2 * DI)];
            float sz = z / (1.f + expf(-z));
            yp[(size_t)l * DI] = (part + Dd * x_t) * sz;
        }
    }
}

// ---------------------------------------------------------------------------
extern "C" void kernel_launch(void* const* d_in, const int* in_sizes, int n_in,
                              void* d_out, int out_size)
{
    const float* x      = (const float*)d_in[0];
    const float* gamma  = (const float*)d_in[1];
    const float* beta   = (const float*)d_in[2];
    const float* W_in   = (const float*)d_in[3];
    const float* conv_w = (const float*)d_in[4];
    const float* conv_b = (const float*)d_in[5];
    const float* W_xproj= (const float*)d_in[6];
    const float* W_dt   = (const float*)d_in[7];
    const float* b_dt   = (const float*)d_in[8];
    const float* A_log  = (const float*)d_in[9];
    const float* Dw     = (const float*)d_in[10];
    const float* W_out  = (const float*)d_in[11];
    float* out = (float*)d_out;

    static float *hn = nullptr, *xz = nullptr, *xssm = nullptr, *xdbl = nullptr,
                 *dtb = nullptr, *yb = nullptr;
    if (!hn) {
        cudaGetSymbolAddress((void**)&hn,   g_hn);
        cudaGetSymbolAddress((void**)&xz,   g_xz);
        cudaGetSymbolAddress((void**)&xssm, g_xssm);
        cudaGetSymbolAddress((void**)&xdbl, g_xdbl);
        cudaGetSymbolAddress((void**)&dtb,  g_dt);
        cudaGetSymbolAddress((void**)&yb,   g_y);
    }

    // 1) LN stats
    ln_stats_kernel<<<dim3(Lsz / 64, Bsz), 256>>>(x);
    // 2) transpose + LN apply
    ln_apply_kernel<<<dim3(Lsz / 32, DM / 32, Bsz), dim3(32, 8)>>>(x, gamma, beta);
    // 3) GEMM1: xz = hn @ W_in^T   (4096 x 3072 x 768)
    gemm_tf32<128, 4, 2, 0><<<dim3(3072 / 128, MROWS / 128), 256>>>(
        hn, DM, W_in, DM, xz, 2 * DI, DM, nullptr, nullptr);
    // 4) conv + silu
    conv_silu_kernel<<<(MROWS * DI + 255) / 256, 256>>>(conv_w, conv_b);
    // 5) xproj: xdbl = xssm @ W_xproj^T   (4096 x 80 x 1536)
    gemm_tf32<80, 8, 1, 0><<<dim3(1, MROWS / 128), 256>>>(
        xssm, DI, W_xproj, DI, xdbl, 80, DI, nullptr, nullptr);
    // 6) dt = softplus(xdbl[:, :48] @ W_dt^T + b_dt)   (4096 x 1536 x 48)
    gemm_tf32<128, 4, 2, 1><<<dim3(DI / 128, MROWS / 128), 256>>>(
        xdbl, 80, W_dt, DTR, dtb, DI, DTR, b_dt, nullptr);
    // 7) scan
    scan_kernel<<<(Bsz * DI * 4 + 255) / 256, 256>>>(A_log, Dw);
    // 8) out = y @ W_out^T, transposed store + residual x   (4096 x 768 x 1536)
    gemm_tf32<128, 4, 2, 2><<<dim3(DM / 128, MROWS / 128), 256>>>(
        yb, DI, W_out, DI, out, 0, DI, nullptr, x);
}

// round 5
// speedup vs baseline: 1.4936x; 1.0462x over previous
#include <cuda_runtime.h>
#include <cuda_bf16.h>
#include <cstdint>

// ---------------------------------------------------------------------------
// MambaBlock: B=4, L=1024, D_MODEL=768, D_INNER=1536, D_STATE=16, DT_RANK=48
// GEMMs: mma.sync.m16n8k8.tf32, 3-stage cp.async pipeline, dynamic smem.
// ---------------------------------------------------------------------------

#define Bsz 4
#define Lsz 1024
#define DM  768
#define DI  1536
#define DS  16
#define DTR 48
#define MROWS (Bsz * Lsz)   // 4096

__device__ __align__(16) float g_hn  [MROWS * DM];
__device__ __align__(16) float g_xz  [MROWS * 2 * DI];
__device__ __align__(16) float g_xssm[MROWS * DI];
__device__ __align__(16) float g_xdbl[MROWS * 80];
__device__ __align__(16) float g_dt  [MROWS * DI];
__device__ __align__(16) float g_y   [MROWS * DI];
__device__ __align__(16) float g_stats[MROWS * 2];

// ---------------------------------------------------------------------------
// 1) LayerNorm statistics
// ---------------------------------------------------------------------------
__global__ void ln_stats_kernel(const float* __restrict__ x)
{
    __shared__ float s_sum[256];
    __shared__ float s_sq[256];
    int tid  = threadIdx.x;
    int lid  = tid & 63;
    int part = tid >> 6;
    int b    = blockIdx.y;
    int l    = blockIdx.x * 64 + lid;
    const float* xb = x + (size_t)b * DM * Lsz + l;

    float sum = 0.f, sq = 0.f;
    int c0 = part * (DM / 4);
    #pragma unroll 8
    for (int c = c0; c < c0 + DM / 4; c++) {
        float v = xb[(size_t)c * Lsz];
        sum += v;
        sq  += v * v;
    }
    s_sum[tid] = sum;
    s_sq[tid]  = sq;
    __syncthreads();
    if (part == 0) {
        float ts = s_sum[tid] + s_sum[tid + 64] + s_sum[tid + 128] + s_sum[tid + 192];
        float tq = s_sq[tid]  + s_sq[tid + 64]  + s_sq[tid + 128]  + s_sq[tid + 192];
        float mu = ts / DM;
        float var = tq / DM - mu * mu;
        float rstd = rsqrtf(var + 1e-5f);
        int bl = b * Lsz + l;
        g_stats[bl * 2 + 0] = mu;
        g_stats[bl * 2 + 1] = rstd;
    }
}

// ---------------------------------------------------------------------------
// 2) Transpose (B,C,L)->(B*L,C) with LN applied
// ---------------------------------------------------------------------------
__global__ void ln_apply_kernel(const float* __restrict__ x,
                                const float* __restrict__ gamma,
                                const float* __restrict__ beta)
{
    __shared__ float tile[32][33];
    int b  = blockIdx.z;
    int c0 = blockIdx.y * 32;
    int l0 = blockIdx.x * 32;
    const float* xb = x + (size_t)b * DM * Lsz;

    #pragma unroll
    for (int i0 = 0; i0 < 4; i0++) {
        int c = c0 + threadIdx.y + i0 * 8;
        tile[threadIdx.y + i0 * 8][threadIdx.x] = xb[(size_t)c * Lsz + l0 + threadIdx.x];
    }
    __syncthreads();
    #pragma unroll
    for (int i0 = 0; i0 < 4; i0++) {
        int l  = l0 + threadIdx.y + i0 * 8;
        int c  = c0 + threadIdx.x;
        int bl = b * Lsz + l;
        float mu   = g_stats[bl * 2 + 0];
        float rstd = g_stats[bl * 2 + 1];
        float v = tile[threadIdx.x][threadIdx.y + i0 * 8];
        g_hn[(size_t)bl * DM + c] = (v - mu) * rstd * gamma[c] + beta[c];
    }
}

// ---------------------------------------------------------------------------
// mma + cp.async helpers
// ---------------------------------------------------------------------------
__device__ __forceinline__ void mma_tf32(float* c, const uint32_t* a, const uint32_t* b)
{
    asm volatile(
        "mma.sync.aligned.m16n8k8.row.col.f32.tf32.tf32.f32 "
        "{%0,%1,%2,%3}, {%4,%5,%6,%7}, {%8,%9}, {%0,%1,%2,%3};"
        : "+f"(c[0]), "+f"(c[1]), "+f"(c[2]), "+f"(c[3])
        : "r"(a[0]), "r"(a[1]), "r"(a[2]), "r"(a[3]), "r"(b[0]), "r"(b[1]));
}

__device__ __forceinline__ void cp16(uint32_t dst_smem, const void* src)
{
    asm volatile("cp.async.cg.shared.global [%0], [%1], 16;"
                 :: "r"(dst_smem), "l"(src));
}
__device__ __forceinline__ void cp_commit()
{
    asm volatile("cp.async.commit_group;");
}
template<int N>
__device__ __forceinline__ void cp_wait()
{
    asm volatile("cp.async.wait_group %0;" :: "n"(N));
}

// ---------------------------------------------------------------------------
// Tensor-core GEMM:  C[M,N] = A[M,K] * B[N,K]^T  (both row-major)
// BM=128, BK=16, 256 threads, 3-stage cp.async pipeline, dynamic smem.
// EPI 0: plain. EPI 1: softplus(acc + bias[n]). EPI 2: transpose store + xres.
// Requires: M % 128 == 0, N == gridDim.x * BN, K % 16 == 0, lda/ldb % 4 == 0.
// ---------------------------------------------------------------------------
template<int BN, int WARPS_M, int WARPS_N, int EPI>
__global__ void __launch_bounds__(256)
gemm_tf32(const float* __restrict__ A, int lda,
          const float* __restrict__ B, int ldb,
          float* __restrict__ C, int ldc,
          int K,
          const float* __restrict__ bias,
          const float* __restrict__ xres)
{
    constexpr int BM = 128;
    constexpr int WM = BM / WARPS_M;
    constexpr int WN = BN / WARPS_N;
    constexpr int MT = WM / 16;
    constexpr int NT = WN / 8;
    constexpr int LDT = 20;              // smem row stride in words (80B)
    constexpr int NA4 = BM * 4;          // float4 copies per A stage (512)
    constexpr int NB4 = BN * 4;          // float4 copies per B stage
    constexpr int ST  = 3;               // pipeline stages
    constexpr int ASTG = BM * LDT;       // words per A stage
    constexpr int BSTG = BN * LDT;       // words per B stage

    extern __shared__ uint32_t smem[];
    uint32_t* Asm = smem;                 // [ST][ASTG]
    uint32_t* Bsm = smem + ST * ASTG;     // [ST][BSTG]

    const int tid   = threadIdx.x;
    const int warp  = tid >> 5;
    const int lane  = tid & 31;
    const int g     = lane >> 2;
    const int t     = lane & 3;

    const int warp_m = warp / WARPS_N;
    const int warp_n = warp % WARPS_N;
    const int wm0 = warp_m * WM;
    const int wn0 = warp_n * WN;

    const int m0 = blockIdx.y * BM;
    const int n0 = blockIdx.x * BN;

    const int a_row = tid >> 2;          // 0..63
    const int a_kq  = (tid & 3) * 4;     // 0,4,8,12

    const int niter = K / 16;

    float acc[MT][NT][4];
    #pragma unroll
    for (int i = 0; i < MT; i++)
        #pragma unroll
        for (int j = 0; j < NT; j++)
            #pragma unroll
            for (int q = 0; q < 4; q++) acc[i][j][q] = 0.f;

    uint32_t sA = (uint32_t)__cvta_generic_to_shared(Asm);
    uint32_t sB = (uint32_t)__cvta_generic_to_shared(Bsm);

    // issue copies for k-iter `it` into stage `s` (no commit)
    auto issue = [&](int s, int it) {
        int k0 = it * 16;
        uint32_t baseA = sA + (uint32_t)s * (ASTG * 4);
        #pragma unroll
        for (int i = 0; i < NA4 / 256; i++) {
            int r = a_row + 64 * i;
            cp16(baseA + (uint32_t)(r * LDT + a_kq) * 4,
                 &A[(size_t)(m0 + r) * lda + k0 + a_kq]);
        }
        uint32_t baseB = sB + (uint32_t)s * (BSTG * 4);
        #pragma unroll
        for (int i = 0; i < (NB4 + 255) / 256; i++) {
            int idx = tid + 256 * i;
            if (idx < NB4) {
                int r  = idx >> 2;
                int kq = (idx & 3) * 4;
                cp16(baseB + (uint32_t)(r * LDT + kq) * 4,
                     &B[(size_t)(n0 + r) * ldb + k0 + kq]);
            }
        }
    };

    // prologue: stages 0 and 1 in flight
    issue(0, 0); cp_commit();
    if (niter > 1) { issue(1, 1); }
    cp_commit();

    int s = 0;
    for (int it = 0; it < niter; it++) {
        cp_wait<1>();          // stage `s` complete
        __syncthreads();       // all warps past reads of the stage being refilled

        if (it + 2 < niter) issue((s + 2) % ST, it + 2);
        cp_commit();           // uniform group count (empty groups ok)

        const uint32_t* as = Asm + s * ASTG;
        const uint32_t* bs = Bsm + s * BSTG;
        #pragma unroll
        for (int ks = 0; ks < 2; ks++) {
            const int kk = ks * 8;
            uint32_t afr[MT][4];
            uint32_t bfr[NT][2];
            #pragma unroll
            for (int i = 0; i < MT; i++) {
                int base = wm0 + 16 * i;
                afr[i][0] = as[(base + g)     * LDT + kk + t];
                afr[i][1] = as[(base + g + 8) * LDT + kk + t];
                afr[i][2] = as[(base + g)     * LDT + kk + t + 4];
                afr[i][3] = as[(base + g + 8) * LDT + kk + t + 4];
            }
            #pragma unroll
            for (int j = 0; j < NT; j++) {
                int bb = wn0 + 8 * j;
                bfr[j][0] = bs[(bb + g) * LDT + kk + t];
                bfr[j][1] = bs[(bb + g) * LDT + kk + t + 4];
            }
            #pragma unroll
            for (int i = 0; i < MT; i++)
                #pragma unroll
                for (int j = 0; j < NT; j++)
                    mma_tf32(acc[i][j], afr[i], bfr[j]);
        }
        __syncthreads();       // all warps done with stage s before refill
        s = (s + 1) % ST;
    }

    // epilogue
    #pragma unroll
    for (int i = 0; i < MT; i++) {
        int r0 = m0 + wm0 + 16 * i + g;
        int r1 = r0 + 8;
        #pragma unroll
        for (int j = 0; j < NT; j++) {
            int col = n0 + wn0 + 8 * j + 2 * t;
            float c0 = acc[i][j][0], c1 = acc[i][j][1];
            float c2 = acc[i][j][2], c3 = acc[i][j][3];
            if (EPI == 1) {
                float b0 = bias[col], b1 = bias[col + 1];
                c0 += b0; c1 += b1; c2 += b0; c3 += b1;
                c0 = (c0 > 20.f) ? c0 : log1pf(expf(c0));
                c1 = (c1 > 20.f) ? c1 : log1pf(expf(c1));
                c2 = (c2 > 20.f) ? c2 : log1pf(expf(c2));
                c3 = (c3 > 20.f) ? c3 : log1pf(expf(c3));
            }
            if (EPI == 2) {
                int b0i = r0 >> 10, l0i = r0 & 1023;
                int b1i = r1 >> 10, l1i = r1 & 1023;
                size_t o00 = ((size_t)(b0i * DM + col))     * Lsz + l0i;
                size_t o01 = ((size_t)(b0i * DM + col + 1)) * Lsz + l0i;
                size_t o10 = ((size_t)(b1i * DM + col))     * Lsz + l1i;
                size_t o11 = ((size_t)(b1i * DM + col + 1)) * Lsz + l1i;
                C[o00] = c0 + xres[o00];
                C[o01] = c1 + xres[o01];
                C[o10] = c2 + xres[o10];
                C[o11] = c3 + xres[o11];
            } else {
                *reinterpret_cast<float2*>(&C[(size_t)r0 * ldc + col]) = make_float2(c0, c1);
                *reinterpret_cast<float2*>(&C[(size_t)r1 * ldc + col]) = make_float2(c2, c3);
            }
        }
    }
}

// dynamic smem sizes
#define GSMEM(BN) (3 * (128 + (BN)) * 20 * 4)

// ---------------------------------------------------------------------------
// 4) depthwise causal conv(4) + bias + silu
// ---------------------------------------------------------------------------
__global__ void conv_silu_kernel(const float* __restrict__ conv_w,
                                 const float* __restrict__ conv_b)
{
    int idx = blockIdx.x * blockDim.x + threadIdx.x;
    if (idx >= MROWS * DI) return;
    int d  = idx % DI;
    int bl = idx / DI;
    int l  = bl & (Lsz - 1);

    float acc = conv_b[d];
    #pragma unroll
    for (int j = 0; j < 4; j++) {
        int ll = l - 3 + j;
        if (ll >= 0)
            acc += conv_w[d * 4 + j] * g_xz[(size_t)(bl - 3 + j) * (2 * DI) + d];
    }
    g_xssm[idx] = acc / (1.f + expf(-acc));
}

// ---------------------------------------------------------------------------
// 7) selective scan: 4 lanes per (b,d), 4 states per lane.
// ---------------------------------------------------------------------------
__global__ void scan_kernel(const float* __restrict__ A_log,
                            const float* __restrict__ Dw)
{
    int pair = blockIdx.x * (blockDim.x >> 2) + (threadIdx.x >> 2);
    if (pair >= Bsz * DI) return;
    int ln = threadIdx.x & 3;
    int b = pair / DI;
    int d = pair % DI;
    int n0 = ln * 4;

    float Av[4], h[4];
    #pragma unroll
    for (int j = 0; j < 4; j++) {
        Av[j] = -expf(A_log[d * DS + n0 + j]);
        h[j] = 0.f;
    }
    float Dd = Dw[d];

    const float* dtp = g_dt   + (size_t)b * Lsz * DI + d;
    const float* xp  = g_xssm + (size_t)b * Lsz * DI + d;
    const float* dbl = g_xdbl + (size_t)b * Lsz * 80;
    const float* zp  = g_xz   + (size_t)b * Lsz * (2 * DI) + DI + d;
    float*       yp  = g_y    + (size_t)b * Lsz * DI + d;

    #pragma unroll 4
    for (int l = 0; l < Lsz; l++) {
        float dt_t = dtp[(size_t)l * DI];
        float x_t  = xp [(size_t)l * DI];
        float4 Bv = *reinterpret_cast<const float4*>(&dbl[l * 80 + DTR + n0]);
        float4 Cv = *reinterpret_cast<const float4*>(&dbl[l * 80 + DTR + DS + n0]);
        float dtx = dt_t * x_t;
        float part;
        h[0] = expf(dt_t * Av[0]) * h[0] + dtx * Bv.x;
        h[1] = expf(dt_t * Av[1]) * h[1] + dtx * Bv.y;
        h[2] = expf(dt_t * Av[2]) * h[2] + dtx * Bv.z;
        h[3] = expf(dt_t * Av[3]) * h[3] + dtx * Bv.w;
        part = h[0] * Cv.x + h[1] * Cv.y + h[2] * Cv.z + h[3] * Cv.w;
        part += __shfl_xor_sync(0xFFFFFFFFu, part, 2);
        part += __shfl_xor_sync(0xFFFFFFFFu, part, 1);
        if (ln == 0) {
            float z  = zp[(size_t)l * (2 * DI)];
            float sz = z / (1.f + expf(-z));
            yp[(size_t)l * DI] = (part + Dd * x_t) * sz;
        }
    }
}

// ---------------------------------------------------------------------------
extern "C" void kernel_launch(void* const* d_in, const int* in_sizes, int n_in,
                              void* d_out, int out_size)
{
    const float* x      = (const float*)d_in[0];
    const float* gamma  = (const float*)d_in[1];
    const float* beta   = (const float*)d_in[2];
    const float* W_in   = (const float*)d_in[3];
    const float* conv_w = (const float*)d_in[4];
    const float* conv_b = (const float*)d_in[5];
    const float* W_xproj= (const float*)d_in[6];
    const float* W_dt   = (const float*)d_in[7];
    const float* b_dt   = (const float*)d_in[8];
    const float* A_log  = (const float*)d_in[9];
    const float* Dw     = (const float*)d_in[10];
    const float* W_out  = (const float*)d_in[11];
    float* out = (float*)d_out;

    static float *hn = nullptr, *xz = nullptr, *xssm = nullptr, *xdbl = nullptr,
                 *dtb = nullptr, *yb = nullptr;
    if (!hn) {
        cudaGetSymbolAddress((void**)&hn,   g_hn);
        cudaGetSymbolAddress((void**)&xz,   g_xz);
        cudaGetSymbolAddress((void**)&xssm, g_xssm);
        cudaGetSymbolAddress((void**)&xdbl, g_xdbl);
        cudaGetSymbolAddress((void**)&dtb,  g_dt);
        cudaGetSymbolAddress((void**)&yb,   g_y);
        // raise dynamic smem caps (once; first call is outside graph capture)
        cudaFuncSetAttribute(gemm_tf32<128, 4, 2, 0>,
                             cudaFuncAttributeMaxDynamicSharedMemorySize, GSMEM(128));
        cudaFuncSetAttribute(gemm_tf32<128, 4, 2, 1>,
                             cudaFuncAttributeMaxDynamicSharedMemorySize, GSMEM(128));
        cudaFuncSetAttribute(gemm_tf32<128, 4, 2, 2>,
                             cudaFuncAttributeMaxDynamicSharedMemorySize, GSMEM(128));
        cudaFuncSetAttribute(gemm_tf32<80, 8, 1, 0>,
                             cudaFuncAttributeMaxDynamicSharedMemorySize, GSMEM(80));
    }

    // 1) LN stats
    ln_stats_kernel<<<dim3(Lsz / 64, Bsz), 256>>>(x);
    // 2) transpose + LN apply
    ln_apply_kernel<<<dim3(Lsz / 32, DM / 32, Bsz), dim3(32, 8)>>>(x, gamma, beta);
    // 3) GEMM1: xz = hn @ W_in^T   (4096 x 3072 x 768)
    gemm_tf32<128, 4, 2, 0><<<dim3(3072 / 128, MROWS / 128), 256, GSMEM(128)>>>(
        hn, DM, W_in, DM, xz, 2 * DI, DM, nullptr, nullptr);
    // 4) conv + silu
    conv_silu_kernel<<<(MROWS * DI + 255) / 256, 256>>>(conv_w, conv_b);
    // 5) xproj: xdbl = xssm @ W_xproj^T   (4096 x 80 x 1536)
    gemm_tf32<80, 8, 1, 0><<<dim3(1, MROWS / 128), 256, GSMEM(80)>>>(
        xssm, DI, W_xproj, DI, xdbl, 80, DI, nullptr, nullptr);
    // 6) dt = softplus(xdbl[:, :48] @ W_dt^T + b_dt)   (4096 x 1536 x 48)
    gemm_tf32<128, 4, 2, 1><<<dim3(DI / 128, MROWS / 128), 256, GSMEM(128)>>>(
        xdbl, 80, W_dt, DTR, dtb, DI, DTR, b_dt, nullptr);
    // 7) scan
    scan_kernel<<<(Bsz * DI * 4 + 255) / 256, 256>>>(A_log, Dw);
    // 8) out = y @ W_out^T, transposed store + residual x   (4096 x 768 x 1536)
    gemm_tf32<128, 4, 2, 2><<<dim3(DM / 128, MROWS / 128), 256, GSMEM(128)>>>(
        yb, DI, W_out, DI, out, 0, DI, nullptr, x);
}

// round 8
// speedup vs baseline: 1.5160x; 1.0150x over previous
#include <cuda_runtime.h>
#include <cuda_bf16.h>
#include <cstdint>

// ---------------------------------------------------------------------------
// MambaBlock: B=4, L=1024, D_MODEL=768, D_INNER=1536, D_STATE=16, DT_RANK=48
// All GEMMs: mma.sync.m16n8k8.tf32 (tcgen05 is unavailable: harness compiles
// for compute_100, which rejects tcgen05).  64x64 warp tiles, 3-stage
// cp.async, single __syncthreads per k-iter.
// ---------------------------------------------------------------------------

#define Bsz 4
#define Lsz 1024
#define DM  768
#define DI  1536
#define DS  16
#define DTR 48
#define MROWS (Bsz * Lsz)   // 4096

__device__ __align__(16) float g_hn  [MROWS * DM];
__device__ __align__(16) float g_xz  [MROWS * 2 * DI];
__device__ __align__(16) float g_xssm[MROWS * DI];
__device__ __align__(16) float g_xdbl[MROWS * 80];
__device__ __align__(16) float g_dt  [MROWS * DI];
__device__ __align__(16) float g_y   [MROWS * DI];
__device__ __align__(16) float g_stats[MROWS * 2];

// dummy kernel: shifts launch indices so ncu's fixed sample slot lands on
// the big GEMM instead of conv_silu.
__global__ void profile_align_kernel() {}

// ---------------------------------------------------------------------------
// 1) LayerNorm statistics
// ---------------------------------------------------------------------------
__global__ void ln_stats_kernel(const float* __restrict__ x)
{
    __shared__ float s_sum[256];
    __shared__ float s_sq[256];
    int tid  = threadIdx.x;
    int lid  = tid & 63;
    int part = tid >> 6;
    int b    = blockIdx.y;
    int l    = blockIdx.x * 64 + lid;
    const float* xb = x + (size_t)b * DM * Lsz + l;

    float sum = 0.f, sq = 0.f;
    int c0 = part * (DM / 4);
    #pragma unroll 8
    for (int c = c0; c < c0 + DM / 4; c++) {
        float v = xb[(size_t)c * Lsz];
        sum += v;
        sq  += v * v;
    }
    s_sum[tid] = sum;
    s_sq[tid]  = sq;
    __syncthreads();
    if (part == 0) {
        float ts = s_sum[tid] + s_sum[tid + 64] + s_sum[tid + 128] + s_sum[tid + 192];
        float tq = s_sq[tid]  + s_sq[tid + 64]  + s_sq[tid + 128]  + s_sq[tid + 192];
        float mu = ts / DM;
        float var = tq / DM - mu * mu;
        float rstd = rsqrtf(var + 1e-5f);
        int bl = b * Lsz + l;
        g_stats[bl * 2 + 0] = mu;
        g_stats[bl * 2 + 1] = rstd;
    }
}

// ---------------------------------------------------------------------------
// 2) Transpose (B,C,L)->(B*L,C) with LN applied
// ---------------------------------------------------------------------------
__global__ void ln_apply_kernel(const float* __restrict__ x,
                                const float* __restrict__ gamma,
                                const float* __restrict__ beta)
{
    __shared__ float tile[32][33];
    int b  = blockIdx.z;
    int c0 = blockIdx.y * 32;
    int l0 = blockIdx.x * 32;
    const float* xb = x + (size_t)b * DM * Lsz;

    #pragma unroll
    for (int i0 = 0; i0 < 4; i0++) {
        int c = c0 + threadIdx.y + i0 * 8;
        tile[threadIdx.y + i0 * 8][threadIdx.x] = xb[(size_t)c * Lsz + l0 + threadIdx.x];
    }
    __syncthreads();
    #pragma unroll
    for (int i0 = 0; i0 < 4; i0++) {
        int l  = l0 + threadIdx.y + i0 * 8;
        int c  = c0 + threadIdx.x;
        int bl = b * Lsz + l;
        float mu   = g_stats[bl * 2 + 0];
        float rstd = g_stats[bl * 2 + 1];
        float v = tile[threadIdx.x][threadIdx.y + i0 * 8];
        g_hn[(size_t)bl * DM + c] = (v - mu) * rstd * gamma[c] + beta[c];
    }
}

// ---------------------------------------------------------------------------
// mma + cp.async helpers
// ---------------------------------------------------------------------------
__device__ __forceinline__ void mma_tf32(float* c, const uint32_t* a, const uint32_t* b)
{
    asm volatile(
        "mma.sync.aligned.m16n8k8.row.col.f32.tf32.tf32.f32 "
        "{%0,%1,%2,%3}, {%4,%5,%6,%7}, {%8,%9}, {%0,%1,%2,%3};"
        : "+f"(c[0]), "+f"(c[1]), "+f"(c[2]), "+f"(c[3])
        : "r"(a[0]), "r"(a[1]), "r"(a[2]), "r"(a[3]), "r"(b[0]), "r"(b[1]));
}

__device__ __forceinline__ void cp16(uint32_t dst_smem, const void* src)
{
    asm volatile("cp.async.cg.shared.global [%0], [%1], 16;"
                 :: "r"(dst_smem), "l"(src));
}
__device__ __forceinline__ void cp_commit()
{
    asm volatile("cp.async.commit_group;");
}
template<int N>
__device__ __forceinline__ void cp_wait()
{
    asm volatile("cp.async.wait_group %0;" :: "n"(N));
}

// ---------------------------------------------------------------------------
// Tensor-core GEMM:  C[M,N] = A[M,K] * B[N,K]^T  (both row-major)
// BM=128, BK=16, WARPS_M x WARPS_N warps (32*WM*WN threads), 3-stage
// cp.async, ONE __syncthreads per k-iter.
// EPI 0: plain. EPI 1: softplus(acc + bias[n]). EPI 2: transpose store + xres.
// Requires: M % 128 == 0, N == gridDim.x * BN, K % 16 == 0, K/16 >= 2.
// ---------------------------------------------------------------------------
template<int BN, int WARPS_M, int WARPS_N, int EPI>
__global__ void __launch_bounds__(32 * WARPS_M * WARPS_N)
gemm_tf32(const float* __restrict__ A, int lda,
          const float* __restrict__ B, int ldb,
          float* __restrict__ C, int ldc,
          int K,
          const float* __restrict__ bias,
          const float* __restrict__ xres)
{
    constexpr int NTH = 32 * WARPS_M * WARPS_N;
    constexpr int BM = 128;
    constexpr int WM = BM / WARPS_M;
    constexpr int WN = BN / WARPS_N;
    constexpr int MT = WM / 16;
    constexpr int NT = WN / 8;
    constexpr int LDT = 20;              // smem row stride in words
    constexpr int NA4 = BM * 4;          // float4 copies per A stage
    constexpr int NB4 = BN * 4;          // float4 copies per B stage
    constexpr int ST  = 3;
    constexpr int ASTG = BM * LDT;
    constexpr int BSTG = BN * LDT;

    extern __shared__ uint32_t smem[];
    uint32_t* Asm = smem;
    uint32_t* Bsm = smem + ST * ASTG;

    const int tid   = threadIdx.x;
    const int warp  = tid >> 5;
    const int lane  = tid & 31;
    const int g     = lane >> 2;
    const int t     = lane & 3;

    const int warp_m = warp / WARPS_N;
    const int warp_n = warp % WARPS_N;
    const int wm0 = warp_m * WM;
    const int wn0 = warp_n * WN;

    const int m0 = blockIdx.y * BM;
    const int n0 = blockIdx.x * BN;

    const int niter = K / 16;

    float acc[MT][NT][4];
    #pragma unroll
    for (int i = 0; i < MT; i++)
        #pragma unroll
        for (int j = 0; j < NT; j++)
            #pragma unroll
            for (int q = 0; q < 4; q++) acc[i][j][q] = 0.f;

    uint32_t sA = (uint32_t)__cvta_generic_to_shared(Asm);
    uint32_t sB = (uint32_t)__cvta_generic_to_shared(Bsm);

    auto issue = [&](int s, int it) {
        int k0 = it * 16;
        uint32_t baseA = sA + (uint32_t)s * (ASTG * 4);
        #pragma unroll
        for (int i = 0; i < NA4 / NTH; i++) {
            int id = tid + NTH * i;
            int r  = id >> 2;
            int kq = (id & 3) * 4;
            cp16(baseA + (uint32_t)(r * LDT + kq) * 4,
                 &A[(size_t)(m0 + r) * lda + k0 + kq]);
        }
        uint32_t baseB = sB + (uint32_t)s * (BSTG * 4);
        #pragma unroll
        for (int i = 0; i < (NB4 + NTH - 1) / NTH; i++) {
            int id = tid + NTH * i;
            if (id < NB4) {
                int r  = id >> 2;
                int kq = (id & 3) * 4;
                cp16(baseB + (uint32_t)(r * LDT + kq) * 4,
                     &B[(size_t)(n0 + r) * ldb + k0 + kq]);
            }
        }
    };

    // prologue: 2 stages in flight
    issue(0, 0); cp_commit();
    issue(1, 1); cp_commit();

    for (int it = 0; it < niter; it++) {
        const int s = it % ST;
        cp_wait<1>();          // stage s group complete (this thread)
        __syncthreads();       // all threads' copies visible; prev compute done

        if (it + 2 < niter) issue((it + 2) % ST, it + 2);
        cp_commit();           // one group per iter (empty ok)

        const uint32_t* as = Asm + s * ASTG;
        const uint32_t* bs = Bsm + s * BSTG;
        #pragma unroll
        for (int ks = 0; ks < 2; ks++) {
            const int kk = ks * 8;
            uint32_t afr[MT][4];
            uint32_t bfr[NT][2];
            #pragma unroll
            for (int i = 0; i < MT; i++) {
                int base = wm0 + 16 * i;
                afr[i][0] = as[(base + g)     * LDT + kk + t];
                afr[i][1] = as[(base + g + 8) * LDT + kk + t];
                afr[i][2] = as[(base + g)     * LDT + kk + t + 4];
                afr[i][3] = as[(base + g + 8) * LDT + kk + t + 4];
            }
            #pragma unroll
            for (int j = 0; j < NT; j++) {
                int bb = wn0 + 8 * j;
                bfr[j][0] = bs[(bb + g) * LDT + kk + t];
                bfr[j][1] = bs[(bb + g) * LDT + kk + t + 4];
            }
            #pragma unroll
            for (int i = 0; i < MT; i++)
                #pragma unroll
                for (int j = 0; j < NT; j++)
                    mma_tf32(acc[i][j], afr[i], bfr[j]);
        }
    }

    // epilogue
    #pragma unroll
    for (int i = 0; i < MT; i++) {
        int r0 = m0 + wm0 + 16 * i + g;
        int r1 = r0 + 8;
        #pragma unroll
        for (int j = 0; j < NT; j++) {
            int col = n0 + wn0 + 8 * j + 2 * t;
            float c0 = acc[i][j][0], c1 = acc[i][j][1];
            float c2 = acc[i][j][2], c3 = acc[i][j][3];
            if (EPI == 1) {
                float b0 = bias[col], b1 = bias[col + 1];
                c0 += b0; c1 += b1; c2 += b0; c3 += b1;
                c0 = (c0 > 20.f) ? c0 : log1pf(expf(c0));
                c1 = (c1 > 20.f) ? c1 : log1pf(expf(c1));
                c2 = (c2 > 20.f) ? c2 : log1pf(expf(c2));
                c3 = (c3 > 20.f) ? c3 : log1pf(expf(c3));
            }
            if (EPI == 2) {
                int b0i = r0 >> 10, l0i = r0 & 1023;
                int b1i = r1 >> 10, l1i = r1 & 1023;
                size_t o00 = ((size_t)(b0i * DM + col))     * Lsz + l0i;
                size_t o01 = ((size_t)(b0i * DM + col + 1)) * Lsz + l0i;
                size_t o10 = ((size_t)(b1i * DM + col))     * Lsz + l1i;
                size_t o11 = ((size_t)(b1i * DM + col + 1)) * Lsz + l1i;
                C[o00] = c0 + xres[o00];
                C[o01] = c1 + xres[o01];
                C[o10] = c2 + xres[o10];
                C[o11] = c3 + xres[o11];
            } else {
                *reinterpret_cast<float2*>(&C[(size_t)r0 * ldc + col]) = make_float2(c0, c1);
                *reinterpret_cast<float2*>(&C[(size_t)r1 * ldc + col]) = make_float2(c2, c3);
            }
        }
    }
}

#define GSMEM(BN) (3 * (128 + (BN)) * 20 * 4)

// ---------------------------------------------------------------------------
// 4) depthwise causal conv(4) + bias + silu
// ---------------------------------------------------------------------------
__global__ void conv_silu_kernel(const float* __restrict__ conv_w,
                                 const float* __restrict__ conv_b)
{
    int idx = blockIdx.x * blockDim.x + threadIdx.x;
    if (idx >= MROWS * DI) return;
    int d  = idx % DI;
    int bl = idx / DI;
    int l  = bl & (Lsz - 1);

    float acc = conv_b[d];
    #pragma unroll
    for (int j = 0; j < 4; j++) {
        int ll = l - 3 + j;
        if (ll >= 0)
            acc += conv_w[d * 4 + j] * g_xz[(size_t)(bl - 3 + j) * (2 * DI) + d];
    }
    g_xssm[idx] = acc / (1.f + expf(-acc));
}

// ---------------------------------------------------------------------------
// 7) selective scan: 4 lanes per (b,d), 4 states per lane.
// ---------------------------------------------------------------------------
__global__ void scan_kernel(const float* __restrict__ A_log,
                            const float* __restrict__ Dw)
{
    int pair = blockIdx.x * (blockDim.x >> 2) + (threadIdx.x >> 2);
    if (pair >= Bsz * DI) return;
    int ln = threadIdx.x & 3;
    int b = pair / DI;
    int d = pair % DI;
    int n0 = ln * 4;

    float Av[4], h[4];
    #pragma unroll
    for (int j = 0; j < 4; j++) {
        Av[j] = -expf(A_log[d * DS + n0 + j]);
        h[j] = 0.f;
    }
    float Dd = Dw[d];

    const float* dtp = g_dt   + (size_t)b * Lsz * DI + d;
    const float* xp  = g_xssm + (size_t)b * Lsz * DI + d;
    const float* dbl = g_xdbl + (size_t)b * Lsz * 80;
    const float* zp  = g_xz   + (size_t)b * Lsz * (2 * DI) + DI + d;
    float*       yp  = g_y    + (size_t)b * Lsz * DI + d;

    #pragma unroll 4
    for (int l = 0; l < Lsz; l++) {
        float dt_t = dtp[(size_t)l * DI];
        float x_t  = xp [(size_t)l * DI];
        float4 Bv = *reinterpret_cast<const float4*>(&dbl[l * 80 + DTR + n0]);
        float4 Cv = *reinterpret_cast<const float4*>(&dbl[l * 80 + DTR + DS + n0]);
        float dtx = dt_t * x_t;
        float part;
        h[0] = expf(dt_t * Av[0]) * h[0] + dtx * Bv.x;
        h[1] = expf(dt_t * Av[1]) * h[1] + dtx * Bv.y;
        h[2] = expf(dt_t * Av[2]) * h[2] + dtx * Bv.z;
        h[3] = expf(dt_t * Av[3]) * h[3] + dtx * Bv.w;
        part = h[0] * Cv.x + h[1] * Cv.y + h[2] * Cv.z + h[3] * Cv.w;
        part += __shfl_xor_sync(0xFFFFFFFFu, part, 2);
        part += __shfl_xor_sync(0xFFFFFFFFu, part, 1);
        if (ln == 0) {
            float z  = zp[(size_t)l * (2 * DI)];
            float sz = z / (1.f + expf(-z));
            yp[(size_t)l * DI] = (part + Dd * x_t) * sz;
        }
    }
}

// ---------------------------------------------------------------------------
extern "C" void kernel_launch(void* const* d_in, const int* in_sizes, int n_in,
                              void* d_out, int out_size)
{
    const float* x      = (const float*)d_in[0];
    const float* gamma  = (const float*)d_in[1];
    const float* beta   = (const float*)d_in[2];
    const float* W_in   = (const float*)d_in[3];
    const float* conv_w = (const float*)d_in[4];
    const float* conv_b = (const float*)d_in[5];
    const float* W_xproj= (const float*)d_in[6];
    const float* W_dt   = (const float*)d_in[7];
    const float* b_dt   = (const float*)d_in[8];
    const float* A_log  = (const float*)d_in[9];
    const float* Dw     = (const float*)d_in[10];
    const float* W_out  = (const float*)d_in[11];
    float* out = (float*)d_out;

    static float *hn = nullptr, *xz = nullptr, *xssm = nullptr, *xdbl = nullptr,
                 *dtb = nullptr, *yb = nullptr;
    if (!hn) {
        cudaGetSymbolAddress((void**)&hn,   g_hn);
        cudaGetSymbolAddress((void**)&xz,   g_xz);
        cudaGetSymbolAddress((void**)&xssm, g_xssm);
        cudaGetSymbolAddress((void**)&xdbl, g_xdbl);
        cudaGetSymbolAddress((void**)&dtb,  g_dt);
        cudaGetSymbolAddress((void**)&yb,   g_y);
        cudaFuncSetAttribute(gemm_tf32<128, 2, 2, 0>,
                             cudaFuncAttributeMaxDynamicSharedMemorySize, GSMEM(128));
        cudaFuncSetAttribute(gemm_tf32<128, 2, 2, 1>,
                             cudaFuncAttributeMaxDynamicSharedMemorySize, GSMEM(128));
        cudaFuncSetAttribute(gemm_tf32<128, 2, 2, 2>,
                             cudaFuncAttributeMaxDynamicSharedMemorySize, GSMEM(128));
        cudaFuncSetAttribute(gemm_tf32<80, 4, 1, 0>,
                             cudaFuncAttributeMaxDynamicSharedMemorySize, GSMEM(80));
    }

    // 0) profiler alignment dummy (shifts ncu's sample slot onto GEMM1)
    profile_align_kernel<<<1, 32>>>();
    // 1) LN stats
    ln_stats_kernel<<<dim3(Lsz / 64, Bsz), 256>>>(x);
    // 2) transpose + LN apply
    ln_apply_kernel<<<dim3(Lsz / 32, DM / 32, Bsz), dim3(32, 8)>>>(x, gamma, beta);
    // 3) GEMM1: xz = hn @ W_in^T   (4096 x 3072 x 768)
    gemm_tf32<128, 2, 2, 0><<<dim3(3072 / 128, MROWS / 128), 128, GSMEM(128)>>>(
        hn, DM, W_in, DM, xz, 2 * DI, DM, nullptr, nullptr);
    // 4) conv + silu
    conv_silu_kernel<<<(MROWS * DI + 255) / 256, 256>>>(conv_w, conv_b);
    // 5) xproj: xdbl = xssm @ W_xproj^T   (4096 x 80 x 1536)
    gemm_tf32<80, 4, 1, 0><<<dim3(1, MROWS / 128), 128, GSMEM(80)>>>(
        xssm, DI, W_xproj, DI, xdbl, 80, DI, nullptr, nullptr);
    // 6) dt = softplus(xdbl[:, :48] @ W_dt^T + b_dt)   (4096 x 1536 x 48)
    gemm_tf32<128, 2, 2, 1><<<dim3(DI / 128, MROWS / 128), 128, GSMEM(128)>>>(
        xdbl, 80, W_dt, DTR, dtb, DI, DTR, b_dt, nullptr);
    // 7) scan
    scan_kernel<<<(Bsz * DI * 4 + 255) / 256, 256>>>(A_log, Dw);
    // 8) out = y @ W_out^T, transposed store + residual x   (4096 x 768 x 1536)
    gemm_tf32<128, 2, 2, 2><<<dim3(DM / 128, MROWS / 128), 128, GSMEM(128)>>>(
        yb, DI, W_out, DI, out, 0, DI, nullptr, x);
}

// round 9
// speedup vs baseline: 3.2218x; 2.1251x over previous
#include <cuda_runtime.h>
#include <cuda_bf16.h>
#include <cstdint>

// ---------------------------------------------------------------------------
// MambaBlock: B=4, L=1024, D_MODEL=768, D_INNER=1536, D_STATE=16, DT_RANK=48
// GEMMs: mma.sync.m16n8k8.tf32, 3-stage cp.async, 64x64 warp tiles.
// Scan: depth-4 software-pipelined register ring (loads 4 steps ahead).
// ---------------------------------------------------------------------------

#define Bsz 4
#define Lsz 1024
#define DM  768
#define DI  1536
#define DS  16
#define DTR 48
#define MROWS (Bsz * Lsz)   // 4096

__device__ __align__(16) float g_hn  [MROWS * DM];
__device__ __align__(16) float g_xz  [MROWS * 2 * DI];
__device__ __align__(16) float g_xssm[MROWS * DI];
__device__ __align__(16) float g_xdbl[MROWS * 80];
__device__ __align__(16) float g_dt  [MROWS * DI];
__device__ __align__(16) float g_y   [MROWS * DI];
__device__ __align__(16) float g_stats[MROWS * 2];

// dummy: keeps the big GEMM at profiled launch index 3
__global__ void profile_align_kernel() {}

// ---------------------------------------------------------------------------
// 1) LayerNorm statistics
// ---------------------------------------------------------------------------
__global__ void ln_stats_kernel(const float* __restrict__ x)
{
    __shared__ float s_sum[256];
    __shared__ float s_sq[256];
    int tid  = threadIdx.x;
    int lid  = tid & 63;
    int part = tid >> 6;
    int b    = blockIdx.y;
    int l    = blockIdx.x * 64 + lid;
    const float* xb = x + (size_t)b * DM * Lsz + l;

    float sum = 0.f, sq = 0.f;
    int c0 = part * (DM / 4);
    #pragma unroll 8
    for (int c = c0; c < c0 + DM / 4; c++) {
        float v = xb[(size_t)c * Lsz];
        sum += v;
        sq  += v * v;
    }
    s_sum[tid] = sum;
    s_sq[tid]  = sq;
    __syncthreads();
    if (part == 0) {
        float ts = s_sum[tid] + s_sum[tid + 64] + s_sum[tid + 128] + s_sum[tid + 192];
        float tq = s_sq[tid]  + s_sq[tid + 64]  + s_sq[tid + 128]  + s_sq[tid + 192];
        float mu = ts / DM;
        float var = tq / DM - mu * mu;
        float rstd = rsqrtf(var + 1e-5f);
        int bl = b * Lsz + l;
        g_stats[bl * 2 + 0] = mu;
        g_stats[bl * 2 + 1] = rstd;
    }
}

// ---------------------------------------------------------------------------
// 2) Transpose (B,C,L)->(B*L,C) with LN applied
// ---------------------------------------------------------------------------
__global__ void ln_apply_kernel(const float* __restrict__ x,
                                const float* __restrict__ gamma,
                                const float* __restrict__ beta)
{
    __shared__ float tile[32][33];
    int b  = blockIdx.z;
    int c0 = blockIdx.y * 32;
    int l0 = blockIdx.x * 32;
    const float* xb = x + (size_t)b * DM * Lsz;

    #pragma unroll
    for (int i0 = 0; i0 < 4; i0++) {
        int c = c0 + threadIdx.y + i0 * 8;
        tile[threadIdx.y + i0 * 8][threadIdx.x] = xb[(size_t)c * Lsz + l0 + threadIdx.x];
    }
    __syncthreads();
    #pragma unroll
    for (int i0 = 0; i0 < 4; i0++) {
        int l  = l0 + threadIdx.y + i0 * 8;
        int c  = c0 + threadIdx.x;
        int bl = b * Lsz + l;
        float mu   = g_stats[bl * 2 + 0];
        float rstd = g_stats[bl * 2 + 1];
        float v = tile[threadIdx.x][threadIdx.y + i0 * 8];
        g_hn[(size_t)bl * DM + c] = (v - mu) * rstd * gamma[c] + beta[c];
    }
}

// ---------------------------------------------------------------------------
// mma + cp.async helpers
// ---------------------------------------------------------------------------
__device__ __forceinline__ void mma_tf32(float* c, const uint32_t* a, const uint32_t* b)
{
    asm volatile(
        "mma.sync.aligned.m16n8k8.row.col.f32.tf32.tf32.f32 "
        "{%0,%1,%2,%3}, {%4,%5,%6,%7}, {%8,%9}, {%0,%1,%2,%3};"
        : "+f"(c[0]), "+f"(c[1]), "+f"(c[2]), "+f"(c[3])
        : "r"(a[0]), "r"(a[1]), "r"(a[2]), "r"(a[3]), "r"(b[0]), "r"(b[1]));
}

__device__ __forceinline__ void cp16(uint32_t dst_smem, const void* src)
{
    asm volatile("cp.async.cg.shared.global [%0], [%1], 16;"
                 :: "r"(dst_smem), "l"(src));
}
__device__ __forceinline__ void cp_commit()
{
    asm volatile("cp.async.commit_group;");
}
template<int N>
__device__ __forceinline__ void cp_wait()
{
    asm volatile("cp.async.wait_group %0;" :: "n"(N));
}

// ---------------------------------------------------------------------------
// Tensor-core GEMM:  C[M,N] = A[M,K] * B[N,K]^T  (both row-major)
// ---------------------------------------------------------------------------
template<int BN, int WARPS_M, int WARPS_N, int EPI>
__global__ void __launch_bounds__(32 * WARPS_M * WARPS_N)
gemm_tf32(const float* __restrict__ A, int lda,
          const float* __restrict__ B, int ldb,
          float* __restrict__ C, int ldc,
          int K,
          const float* __restrict__ bias,
          const float* __restrict__ xres)
{
    constexpr int NTH = 32 * WARPS_M * WARPS_N;
    constexpr int BM = 128;
    constexpr int WM = BM / WARPS_M;
    constexpr int WN = BN / WARPS_N;
    constexpr int MT = WM / 16;
    constexpr int NT = WN / 8;
    constexpr int LDT = 20;
    constexpr int NA4 = BM * 4;
    constexpr int NB4 = BN * 4;
    constexpr int ST  = 3;
    constexpr int ASTG = BM * LDT;
    constexpr int BSTG = BN * LDT;

    extern __shared__ uint32_t smem[];
    uint32_t* Asm = smem;
    uint32_t* Bsm = smem + ST * ASTG;

    const int tid   = threadIdx.x;
    const int warp  = tid >> 5;
    const int lane  = tid & 31;
    const int g     = lane >> 2;
    const int t     = lane & 3;

    const int warp_m = warp / WARPS_N;
    const int warp_n = warp % WARPS_N;
    const int wm0 = warp_m * WM;
    const int wn0 = warp_n * WN;

    const int m0 = blockIdx.y * BM;
    const int n0 = blockIdx.x * BN;

    const int niter = K / 16;

    float acc[MT][NT][4];
    #pragma unroll
    for (int i = 0; i < MT; i++)
        #pragma unroll
        for (int j = 0; j < NT; j++)
            #pragma unroll
            for (int q = 0; q < 4; q++) acc[i][j][q] = 0.f;

    uint32_t sA = (uint32_t)__cvta_generic_to_shared(Asm);
    uint32_t sB = (uint32_t)__cvta_generic_to_shared(Bsm);

    auto issue = [&](int s, int it) {
        int k0 = it * 16;
        uint32_t baseA = sA + (uint32_t)s * (ASTG * 4);
        #pragma unroll
        for (int i = 0; i < NA4 / NTH; i++) {
            int id = tid + NTH * i;
            int r  = id >> 2;
            int kq = (id & 3) * 4;
            cp16(baseA + (uint32_t)(r * LDT + kq) * 4,
                 &A[(size_t)(m0 + r) * lda + k0 + kq]);
        }
        uint32_t baseB = sB + (uint32_t)s * (BSTG * 4);
        #pragma unroll
        for (int i = 0; i < (NB4 + NTH - 1) / NTH; i++) {
            int id = tid + NTH * i;
            if (id < NB4) {
                int r  = id >> 2;
                int kq = (id & 3) * 4;
                cp16(baseB + (uint32_t)(r * LDT + kq) * 4,
                     &B[(size_t)(n0 + r) * ldb + k0 + kq]);
            }
        }
    };

    issue(0, 0); cp_commit();
    issue(1, 1); cp_commit();

    for (int it = 0; it < niter; it++) {
        const int s = it % ST;
        cp_wait<1>();
        __syncthreads();

        if (it + 2 < niter) issue((it + 2) % ST, it + 2);
        cp_commit();

        const uint32_t* as = Asm + s * ASTG;
        const uint32_t* bs = Bsm + s * BSTG;
        #pragma unroll
        for (int ks = 0; ks < 2; ks++) {
            const int kk = ks * 8;
            uint32_t afr[MT][4];
            uint32_t bfr[NT][2];
            #pragma unroll
            for (int i = 0; i < MT; i++) {
                int base = wm0 + 16 * i;
                afr[i][0] = as[(base + g)     * LDT + kk + t];
                afr[i][1] = as[(base + g + 8) * LDT + kk + t];
                afr[i][2] = as[(base + g)     * LDT + kk + t + 4];
                afr[i][3] = as[(base + g + 8) * LDT + kk + t + 4];
            }
            #pragma unroll
            for (int j = 0; j < NT; j++) {
                int bb = wn0 + 8 * j;
                bfr[j][0] = bs[(bb + g) * LDT + kk + t];
                bfr[j][1] = bs[(bb + g) * LDT + kk + t + 4];
            }
            #pragma unroll
            for (int i = 0; i < MT; i++)
                #pragma unroll
                for (int j = 0; j < NT; j++)
                    mma_tf32(acc[i][j], afr[i], bfr[j]);
        }
    }

    #pragma unroll
    for (int i = 0; i < MT; i++) {
        int r0 = m0 + wm0 + 16 * i + g;
        int r1 = r0 + 8;
        #pragma unroll
        for (int j = 0; j < NT; j++) {
            int col = n0 + wn0 + 8 * j + 2 * t;
            float c0 = acc[i][j][0], c1 = acc[i][j][1];
            float c2 = acc[i][j][2], c3 = acc[i][j][3];
            if (EPI == 1) {
                float b0 = bias[col], b1 = bias[col + 1];
                c0 += b0; c1 += b1; c2 += b0; c3 += b1;
                c0 = (c0 > 20.f) ? c0 : log1pf(expf(c0));
                c1 = (c1 > 20.f) ? c1 : log1pf(expf(c1));
                c2 = (c2 > 20.f) ? c2 : log1pf(expf(c2));
                c3 = (c3 > 20.f) ? c3 : log1pf(expf(c3));
            }
            if (EPI == 2) {
                int b0i = r0 >> 10, l0i = r0 & 1023;
                int b1i = r1 >> 10, l1i = r1 & 1023;
                size_t o00 = ((size_t)(b0i * DM + col))     * Lsz + l0i;
                size_t o01 = ((size_t)(b0i * DM + col + 1)) * Lsz + l0i;
                size_t o10 = ((size_t)(b1i * DM + col))     * Lsz + l1i;
                size_t o11 = ((size_t)(b1i * DM + col + 1)) * Lsz + l1i;
                C[o00] = c0 + xres[o00];
                C[o01] = c1 + xres[o01];
                C[o10] = c2 + xres[o10];
                C[o11] = c3 + xres[o11];
            } else {
                *reinterpret_cast<float2*>(&C[(size_t)r0 * ldc + col]) = make_float2(c0, c1);
                *reinterpret_cast<float2*>(&C[(size_t)r1 * ldc + col]) = make_float2(c2, c3);
            }
        }
    }
}

#define GSMEM(BN) (3 * (128 + (BN)) * 20 * 4)

// ---------------------------------------------------------------------------
// 4) depthwise causal conv(4) + bias + silu
// ---------------------------------------------------------------------------
__global__ void conv_silu_kernel(const float* __restrict__ conv_w,
                                 const float* __restrict__ conv_b)
{
    int idx = blockIdx.x * blockDim.x + threadIdx.x;
    if (idx >= MROWS * DI) return;
    int d  = idx % DI;
    int bl = idx / DI;
    int l  = bl & (Lsz - 1);

    float acc = conv_b[d];
    #pragma unroll
    for (int j = 0; j < 4; j++) {
        int ll = l - 3 + j;
        if (ll >= 0)
            acc += conv_w[d * 4 + j] * g_xz[(size_t)(bl - 3 + j) * (2 * DI) + d];
    }
    g_xssm[idx] = acc / (1.f + expf(-acc));
}

// ---------------------------------------------------------------------------
// 7) selective scan: 4 lanes per (b,d), 4 states per lane.
// Software-pipelined: register ring holds PF=4 steps of (dt,x,B,C,z);
// loads issue PF iterations ahead of consumption -> MLP ~20 instead of ~1.
// ---------------------------------------------------------------------------
#define PF 4

__global__ void __launch_bounds__(128)
scan_kernel(const float* __restrict__ A_log,
            const float* __restrict__ Dw)
{
    int pair = blockIdx.x * (blockDim.x >> 2) + (threadIdx.x >> 2);
    if (pair >= Bsz * DI) return;
    int ln = threadIdx.x & 3;
    int b = pair / DI;
    int d = pair % DI;
    int n0 = ln * 4;

    float Av[4], h[4];
    #pragma unroll
    for (int j = 0; j < 4; j++) {
        Av[j] = -expf(A_log[d * DS + n0 + j]);
        h[j] = 0.f;
    }
    float Dd = Dw[d];

    const float* dtp = g_dt   + (size_t)b * Lsz * DI + d;
    const float* xp  = g_xssm + (size_t)b * Lsz * DI + d;
    const float* dbl = g_xdbl + (size_t)b * Lsz * 80;
    const float* zp  = g_xz   + (size_t)b * Lsz * (2 * DI) + DI + d;
    float*       yp  = g_y    + (size_t)b * Lsz * DI + d;

    float  pdt[PF], px[PF], pz[PF];
    float4 pB[PF], pC[PF];

    #pragma unroll
    for (int j = 0; j < PF; j++) {
        pdt[j] = dtp[(size_t)j * DI];
        px[j]  = xp [(size_t)j * DI];
        pB[j]  = *reinterpret_cast<const float4*>(&dbl[j * 80 + DTR + n0]);
        pC[j]  = *reinterpret_cast<const float4*>(&dbl[j * 80 + DTR + DS + n0]);
        pz[j]  = zp[(size_t)j * (2 * DI)];
    }

    for (int l0 = 0; l0 < Lsz; l0 += PF) {
        #pragma unroll
        for (int j = 0; j < PF; j++) {
            const int l = l0 + j;
            // consume slot j
            float  dt_t = pdt[j];
            float  x_t  = px[j];
            float4 Bv   = pB[j];
            float4 Cv   = pC[j];
            float  zv   = pz[j];
            // refill slot j for step l+PF (issues early; consumed PF steps later)
            const int lf = l + PF;
            if (lf < Lsz) {
                pdt[j] = dtp[(size_t)lf * DI];
                px[j]  = xp [(size_t)lf * DI];
                pB[j]  = *reinterpret_cast<const float4*>(&dbl[lf * 80 + DTR + n0]);
                pC[j]  = *reinterpret_cast<const float4*>(&dbl[lf * 80 + DTR + DS + n0]);
                pz[j]  = zp[(size_t)lf * (2 * DI)];
            }
            float dtx = dt_t * x_t;
            h[0] = expf(dt_t * Av[0]) * h[0] + dtx * Bv.x;
            h[1] = expf(dt_t * Av[1]) * h[1] + dtx * Bv.y;
            h[2] = expf(dt_t * Av[2]) * h[2] + dtx * Bv.z;
            h[3] = expf(dt_t * Av[3]) * h[3] + dtx * Bv.w;
            float part = h[0] * Cv.x + h[1] * Cv.y + h[2] * Cv.z + h[3] * Cv.w;
            part += __shfl_xor_sync(0xFFFFFFFFu, part, 2);
            part += __shfl_xor_sync(0xFFFFFFFFu, part, 1);
            if (ln == 0) {
                float sz = zv / (1.f + expf(-zv));
                yp[(size_t)l * DI] = (part + Dd * x_t) * sz;
            }
        }
    }
}

// ---------------------------------------------------------------------------
extern "C" void kernel_launch(void* const* d_in, const int* in_sizes, int n_in,
                              void* d_out, int out_size)
{
    const float* x      = (const float*)d_in[0];
    const float* gamma  = (const float*)d_in[1];
    const float* beta   = (const float*)d_in[2];
    const float* W_in   = (const float*)d_in[3];
    const float* conv_w = (const float*)d_in[4];
    const float* conv_b = (const float*)d_in[5];
    const float* W_xproj= (const float*)d_in[6];
    const float* W_dt   = (const float*)d_in[7];
    const float* b_dt   = (const float*)d_in[8];
    const float* A_log  = (const float*)d_in[9];
    const float* Dw     = (const float*)d_in[10];
    const float* W_out  = (const float*)d_in[11];
    float* out = (float*)d_out;

    static float *hn = nullptr, *xz = nullptr, *xssm = nullptr, *xdbl = nullptr,
                 *dtb = nullptr, *yb = nullptr;
    if (!hn) {
        cudaGetSymbolAddress((void**)&hn,   g_hn);
        cudaGetSymbolAddress((void**)&xz,   g_xz);
        cudaGetSymbolAddress((void**)&xssm, g_xssm);
        cudaGetSymbolAddress((void**)&xdbl, g_xdbl);
        cudaGetSymbolAddress((void**)&dtb,  g_dt);
        cudaGetSymbolAddress((void**)&yb,   g_y);
        cudaFuncSetAttribute(gemm_tf32<128, 2, 2, 0>,
                             cudaFuncAttributeMaxDynamicSharedMemorySize, GSMEM(128));
        cudaFuncSetAttribute(gemm_tf32<128, 2, 2, 1>,
                             cudaFuncAttributeMaxDynamicSharedMemorySize, GSMEM(128));
        cudaFuncSetAttribute(gemm_tf32<128, 2, 2, 2>,
                             cudaFuncAttributeMaxDynamicSharedMemorySize, GSMEM(128));
        cudaFuncSetAttribute(gemm_tf32<80, 4, 1, 0>,
                             cudaFuncAttributeMaxDynamicSharedMemorySize, GSMEM(80));
    }

    // 0) profiler alignment dummy (keeps GEMM1 at profiled launch index 3)
    profile_align_kernel<<<1, 32>>>();
    // 1) LN stats
    ln_stats_kernel<<<dim3(Lsz / 64, Bsz), 256>>>(x);
    // 2) transpose + LN apply
    ln_apply_kernel<<<dim3(Lsz / 32, DM / 32, Bsz), dim3(32, 8)>>>(x, gamma, beta);
    // 3) GEMM1: xz = hn @ W_in^T   (4096 x 3072 x 768)
    gemm_tf32<128, 2, 2, 0><<<dim3(3072 / 128, MROWS / 128), 128, GSMEM(128)>>>(
        hn, DM, W_in, DM, xz, 2 * DI, DM, nullptr, nullptr);
    // 4) conv + silu
    conv_silu_kernel<<<(MROWS * DI + 255) / 256, 256>>>(conv_w, conv_b);
    // 5) xproj: xdbl = xssm @ W_xproj^T   (4096 x 80 x 1536)
    gemm_tf32<80, 4, 1, 0><<<dim3(1, MROWS / 128), 128, GSMEM(80)>>>(
        xssm, DI, W_xproj, DI, xdbl, 80, DI, nullptr, nullptr);
    // 6) dt = softplus(xdbl[:, :48] @ W_dt^T + b_dt)   (4096 x 1536 x 48)
    gemm_tf32<128, 2, 2, 1><<<dim3(DI / 128, MROWS / 128), 128, GSMEM(128)>>>(
        xdbl, 80, W_dt, DTR, dtb, DI, DTR, b_dt, nullptr);
    // 7) scan (software-pipelined)
    scan_kernel<<<(Bsz * DI * 4 + 127) / 128, 128>>>(A_log, Dw);
    // 8) out = y @ W_out^T, transposed store + residual x   (4096 x 768 x 1536)
    gemm_tf32<128, 2, 2, 2><<<dim3(DM / 128, MROWS / 128), 128, GSMEM(128)>>>(
        yb, DI, W_out, DI, out, 0, DI, nullptr, x);
}

// round 10
// speedup vs baseline: 3.3073x; 1.0265x over previous
#include <cuda_runtime.h>
#include <cuda_bf16.h>
#include <cstdint>

// ---------------------------------------------------------------------------
// MambaBlock: B=4, L=1024, D_MODEL=768, D_INNER=1536, D_STATE=16, DT_RANK=48
// GEMMs: mma.sync.m16n8k8.tf32, 3-stage cp.async, 64x64 warp tiles,
// forced 3 CTAs/SM.  xproj: split-K x6 + reduce.  Scan: depth-4 SW pipeline.
// ---------------------------------------------------------------------------

#define Bsz 4
#define Lsz 1024
#define DM  768
#define DI  1536
#define DS  16
#define DTR 48
#define MROWS (Bsz * Lsz)   // 4096
#define SPLITK 6
#define XPK (DI / SPLITK)   // 256 K per split chunk

__device__ __align__(16) float g_hn  [MROWS * DM];
__device__ __align__(16) float g_xz  [MROWS * 2 * DI];
__device__ __align__(16) float g_xssm[MROWS * DI];
__device__ __align__(16) float g_xdbl[MROWS * 80];
__device__ __align__(16) float g_xdbl_part[SPLITK * MROWS * 80];
__device__ __align__(16) float g_dt  [MROWS * DI];
__device__ __align__(16) float g_y   [MROWS * DI];
__device__ __align__(16) float g_stats[MROWS * 2];

// dummy: keeps the big GEMM at profiled launch index 3
__global__ void profile_align_kernel() {}

// ---------------------------------------------------------------------------
// 1) LayerNorm statistics
// ---------------------------------------------------------------------------
__global__ void ln_stats_kernel(const float* __restrict__ x)
{
    __shared__ float s_sum[256];
    __shared__ float s_sq[256];
    int tid  = threadIdx.x;
    int lid  = tid & 63;
    int part = tid >> 6;
    int b    = blockIdx.y;
    int l    = blockIdx.x * 64 + lid;
    const float* xb = x + (size_t)b * DM * Lsz + l;

    float sum = 0.f, sq = 0.f;
    int c0 = part * (DM / 4);
    #pragma unroll 8
    for (int c = c0; c < c0 + DM / 4; c++) {
        float v = xb[(size_t)c * Lsz];
        sum += v;
        sq  += v * v;
    }
    s_sum[tid] = sum;
    s_sq[tid]  = sq;
    __syncthreads();
    if (part == 0) {
        float ts = s_sum[tid] + s_sum[tid + 64] + s_sum[tid + 128] + s_sum[tid + 192];
        float tq = s_sq[tid]  + s_sq[tid + 64]  + s_sq[tid + 128]  + s_sq[tid + 192];
        float mu = ts / DM;
        float var = tq / DM - mu * mu;
        float rstd = rsqrtf(var + 1e-5f);
        int bl = b * Lsz + l;
        g_stats[bl * 2 + 0] = mu;
        g_stats[bl * 2 + 1] = rstd;
    }
}

// ---------------------------------------------------------------------------
// 2) Transpose (B,C,L)->(B*L,C) with LN applied
// ---------------------------------------------------------------------------
__global__ void ln_apply_kernel(const float* __restrict__ x,
                                const float* __restrict__ gamma,
                                const float* __restrict__ beta)
{
    __shared__ float tile[32][33];
    int b  = blockIdx.z;
    int c0 = blockIdx.y * 32;
    int l0 = blockIdx.x * 32;
    const float* xb = x + (size_t)b * DM * Lsz;

    #pragma unroll
    for (int i0 = 0; i0 < 4; i0++) {
        int c = c0 + threadIdx.y + i0 * 8;
        tile[threadIdx.y + i0 * 8][threadIdx.x] = xb[(size_t)c * Lsz + l0 + threadIdx.x];
    }
    __syncthreads();
    #pragma unroll
    for (int i0 = 0; i0 < 4; i0++) {
        int l  = l0 + threadIdx.y + i0 * 8;
        int c  = c0 + threadIdx.x;
        int bl = b * Lsz + l;
        float mu   = g_stats[bl * 2 + 0];
        float rstd = g_stats[bl * 2 + 1];
        float v = tile[threadIdx.x][threadIdx.y + i0 * 8];
        g_hn[(size_t)bl * DM + c] = (v - mu) * rstd * gamma[c] + beta[c];
    }
}

// ---------------------------------------------------------------------------
// mma + cp.async helpers
// ---------------------------------------------------------------------------
__device__ __forceinline__ void mma_tf32(float* c, const uint32_t* a, const uint32_t* b)
{
    asm volatile(
        "mma.sync.aligned.m16n8k8.row.col.f32.tf32.tf32.f32 "
        "{%0,%1,%2,%3}, {%4,%5,%6,%7}, {%8,%9}, {%0,%1,%2,%3};"
        : "+f"(c[0]), "+f"(c[1]), "+f"(c[2]), "+f"(c[3])
        : "r"(a[0]), "r"(a[1]), "r"(a[2]), "r"(a[3]), "r"(b[0]), "r"(b[1]));
}

__device__ __forceinline__ void cp16(uint32_t dst_smem, const void* src)
{
    asm volatile("cp.async.cg.shared.global [%0], [%1], 16;"
                 :: "r"(dst_smem), "l"(src));
}
__device__ __forceinline__ void cp_commit()
{
    asm volatile("cp.async.commit_group;");
}
template<int N>
__device__ __forceinline__ void cp_wait()
{
    asm volatile("cp.async.wait_group %0;" :: "n"(N));
}

// ---------------------------------------------------------------------------
// Tensor-core GEMM:  C[M,N] = A[M,K] * B[N,K]^T  (both row-major)
// blockIdx.z selects a disjoint K chunk (split-K); C offset by z*split_stride.
// ---------------------------------------------------------------------------
template<int BN, int WARPS_M, int WARPS_N, int EPI>
__global__ void __launch_bounds__(32 * WARPS_M * WARPS_N, 3)
gemm_tf32(const float* __restrict__ A, int lda,
          const float* __restrict__ B, int ldb,
          float* __restrict__ C, int ldc,
          int K,
          const float* __restrict__ bias,
          const float* __restrict__ xres,
          int split_stride)
{
    constexpr int NTH = 32 * WARPS_M * WARPS_N;
    constexpr int BM = 128;
    constexpr int WM = BM / WARPS_M;
    constexpr int WN = BN / WARPS_N;
    constexpr int MT = WM / 16;
    constexpr int NT = WN / 8;
    constexpr int LDT = 20;
    constexpr int NA4 = BM * 4;
    constexpr int NB4 = BN * 4;
    constexpr int ST  = 3;
    constexpr int ASTG = BM * LDT;
    constexpr int BSTG = BN * LDT;

    extern __shared__ uint32_t smem[];
    uint32_t* Asm = smem;
    uint32_t* Bsm = smem + ST * ASTG;

    const int tid   = threadIdx.x;
    const int warp  = tid >> 5;
    const int lane  = tid & 31;
    const int g     = lane >> 2;
    const int t     = lane & 3;

    const int warp_m = warp / WARPS_N;
    const int warp_n = warp % WARPS_N;
    const int wm0 = warp_m * WM;
    const int wn0 = warp_n * WN;

    const int m0 = blockIdx.y * BM;
    const int n0 = blockIdx.x * BN;

    // split-K: chunk z covers K columns [z*K, (z+1)*K)
    const float* Ae = A + (size_t)blockIdx.z * K;
    const float* Be = B + (size_t)blockIdx.z * K;
    float* Ce = C + (size_t)blockIdx.z * split_stride;

    const int niter = K / 16;

    float acc[MT][NT][4];
    #pragma unroll
    for (int i = 0; i < MT; i++)
        #pragma unroll
        for (int j = 0; j < NT; j++)
            #pragma unroll
            for (int q = 0; q < 4; q++) acc[i][j][q] = 0.f;

    uint32_t sA = (uint32_t)__cvta_generic_to_shared(Asm);
    uint32_t sB = (uint32_t)__cvta_generic_to_shared(Bsm);

    auto issue = [&](int s, int it) {
        int k0 = it * 16;
        uint32_t baseA = sA + (uint32_t)s * (ASTG * 4);
        #pragma unroll
        for (int i = 0; i < NA4 / NTH; i++) {
            int id = tid + NTH * i;
            int r  = id >> 2;
            int kq = (id & 3) * 4;
            cp16(baseA + (uint32_t)(r * LDT + kq) * 4,
                 &Ae[(size_t)(m0 + r) * lda + k0 + kq]);
        }
        uint32_t baseB = sB + (uint32_t)s * (BSTG * 4);
        #pragma unroll
        for (int i = 0; i < (NB4 + NTH - 1) / NTH; i++) {
            int id = tid + NTH * i;
            if (id < NB4) {
                int r  = id >> 2;
                int kq = (id & 3) * 4;
                cp16(baseB + (uint32_t)(r * LDT + kq) * 4,
                     &Be[(size_t)(n0 + r) * ldb + k0 + kq]);
            }
        }
    };

    issue(0, 0); cp_commit();
    issue(1, 1); cp_commit();

    for (int it = 0; it < niter; it++) {
        const int s = it % ST;
        cp_wait<1>();
        __syncthreads();

        if (it + 2 < niter) issue((it + 2) % ST, it + 2);
        cp_commit();

        const uint32_t* as = Asm + s * ASTG;
        const uint32_t* bs = Bsm + s * BSTG;
        #pragma unroll
        for (int ks = 0; ks < 2; ks++) {
            const int kk = ks * 8;
            uint32_t afr[MT][4];
            uint32_t bfr[NT][2];
            #pragma unroll
            for (int i = 0; i < MT; i++) {
                int base = wm0 + 16 * i;
                afr[i][0] = as[(base + g)     * LDT + kk + t];
                afr[i][1] = as[(base + g + 8) * LDT + kk + t];
                afr[i][2] = as[(base + g)     * LDT + kk + t + 4];
                afr[i][3] = as[(base + g + 8) * LDT + kk + t + 4];
            }
            #pragma unroll
            for (int j = 0; j < NT; j++) {
                int bb = wn0 + 8 * j;
                bfr[j][0] = bs[(bb + g) * LDT + kk + t];
                bfr[j][1] = bs[(bb + g) * LDT + kk + t + 4];
            }
            #pragma unroll
            for (int i = 0; i < MT; i++)
                #pragma unroll
                for (int j = 0; j < NT; j++)
                    mma_tf32(acc[i][j], afr[i], bfr[j]);
        }
    }

    #pragma unroll
    for (int i = 0; i < MT; i++) {
        int r0 = m0 + wm0 + 16 * i + g;
        int r1 = r0 + 8;
        #pragma unroll
        for (int j = 0; j < NT; j++) {
            int col = n0 + wn0 + 8 * j + 2 * t;
            float c0 = acc[i][j][0], c1 = acc[i][j][1];
            float c2 = acc[i][j][2], c3 = acc[i][j][3];
            if (EPI == 1) {
                float b0 = bias[col], b1 = bias[col + 1];
                c0 += b0; c1 += b1; c2 += b0; c3 += b1;
                c0 = (c0 > 20.f) ? c0 : log1pf(expf(c0));
                c1 = (c1 > 20.f) ? c1 : log1pf(expf(c1));
                c2 = (c2 > 20.f) ? c2 : log1pf(expf(c2));
                c3 = (c3 > 20.f) ? c3 : log1pf(expf(c3));
            }
            if (EPI == 2) {
                int b0i = r0 >> 10, l0i = r0 & 1023;
                int b1i = r1 >> 10, l1i = r1 & 1023;
                size_t o00 = ((size_t)(b0i * DM + col))     * Lsz + l0i;
                size_t o01 = ((size_t)(b0i * DM + col + 1)) * Lsz + l0i;
                size_t o10 = ((size_t)(b1i * DM + col))     * Lsz + l1i;
                size_t o11 = ((size_t)(b1i * DM + col + 1)) * Lsz + l1i;
                Ce[o00] = c0 + xres[o00];
                Ce[o01] = c1 + xres[o01];
                Ce[o10] = c2 + xres[o10];
                Ce[o11] = c3 + xres[o11];
            } else {
                *reinterpret_cast<float2*>(&Ce[(size_t)r0 * ldc + col]) = make_float2(c0, c1);
                *reinterpret_cast<float2*>(&Ce[(size_t)r1 * ldc + col]) = make_float2(c2, c3);
            }
        }
    }
}

#define GSMEM(BN) (3 * (128 + (BN)) * 20 * 4)

// reduce the SPLITK partial xproj results -> g_xdbl (deterministic order)
__global__ void xdbl_reduce_kernel()
{
    int idx = blockIdx.x * blockDim.x + threadIdx.x;
    if (idx >= MROWS * 80) return;
    float s = 0.f;
    #pragma unroll
    for (int p = 0; p < SPLITK; p++)
        s += g_xdbl_part[(size_t)p * (MROWS * 80) + idx];
    g_xdbl[idx] = s;
}

// ---------------------------------------------------------------------------
// 4) depthwise causal conv(4) + bias + silu
// ---------------------------------------------------------------------------
__global__ void conv_silu_kernel(const float* __restrict__ conv_w,
                                 const float* __restrict__ conv_b)
{
    int idx = blockIdx.x * blockDim.x + threadIdx.x;
    if (idx >= MROWS * DI) return;
    int d  = idx % DI;
    int bl = idx / DI;
    int l  = bl & (Lsz - 1);

    float acc = conv_b[d];
    #pragma unroll
    for (int j = 0; j < 4; j++) {
        int ll = l - 3 + j;
        if (ll >= 0)
            acc += conv_w[d * 4 + j] * g_xz[(size_t)(bl - 3 + j) * (2 * DI) + d];
    }
    g_xssm[idx] = acc / (1.f + expf(-acc));
}

// ---------------------------------------------------------------------------
// 7) selective scan: 4 lanes per (b,d), depth-4 software pipeline.
// ---------------------------------------------------------------------------
#define PF 4

__global__ void __launch_bounds__(128)
scan_kernel(const float* __restrict__ A_log,
            const float* __restrict__ Dw)
{
    int pair = blockIdx.x * (blockDim.x >> 2) + (threadIdx.x >> 2);
    if (pair >= Bsz * DI) return;
    int ln = threadIdx.x & 3;
    int b = pair / DI;
    int d = pair % DI;
    int n0 = ln * 4;

    float Av[4], h[4];
    #pragma unroll
    for (int j = 0; j < 4; j++) {
        Av[j] = -expf(A_log[d * DS + n0 + j]);
        h[j] = 0.f;
    }
    float Dd = Dw[d];

    const float* dtp = g_dt   + (size_t)b * Lsz * DI + d;
    const float* xp  = g_xssm + (size_t)b * Lsz * DI + d;
    const float* dbl = g_xdbl + (size_t)b * Lsz * 80;
    const float* zp  = g_xz   + (size_t)b * Lsz * (2 * DI) + DI + d;
    float*       yp  = g_y    + (size_t)b * Lsz * DI + d;

    float  pdt[PF], px[PF], pz[PF];
    float4 pB[PF], pC[PF];

    #pragma unroll
    for (int j = 0; j < PF; j++) {
        pdt[j] = dtp[(size_t)j * DI];
        px[j]  = xp [(size_t)j * DI];
        pB[j]  = *reinterpret_cast<const float4*>(&dbl[j * 80 + DTR + n0]);
        pC[j]  = *reinterpret_cast<const float4*>(&dbl[j * 80 + DTR + DS + n0]);
        pz[j]  = zp[(size_t)j * (2 * DI)];
    }

    for (int l0 = 0; l0 < Lsz; l0 += PF) {
        #pragma unroll
        for (int j = 0; j < PF; j++) {
            const int l = l0 + j;
            float  dt_t = pdt[j];
            float  x_t  = px[j];
            float4 Bv   = pB[j];
            float4 Cv   = pC[j];
            float  zv   = pz[j];
            const int lf = l + PF;
            if (lf < Lsz) {
                pdt[j] = dtp[(size_t)lf * DI];
                px[j]  = xp [(size_t)lf * DI];
                pB[j]  = *reinterpret_cast<const float4*>(&dbl[lf * 80 + DTR + n0]);
                pC[j]  = *reinterpret_cast<const float4*>(&dbl[lf * 80 + DTR + DS + n0]);
                pz[j]  = zp[(size_t)lf * (2 * DI)];
            }
            float dtx = dt_t * x_t;
            h[0] = expf(dt_t * Av[0]) * h[0] + dtx * Bv.x;
            h[1] = expf(dt_t * Av[1]) * h[1] + dtx * Bv.y;
            h[2] = expf(dt_t * Av[2]) * h[2] + dtx * Bv.z;
            h[3] = expf(dt_t * Av[3]) * h[3] + dtx * Bv.w;
            float part = h[0] * Cv.x + h[1] * Cv.y + h[2] * Cv.z + h[3] * Cv.w;
            part += __shfl_xor_sync(0xFFFFFFFFu, part, 2);
            part += __shfl_xor_sync(0xFFFFFFFFu, part, 1);
            if (ln == 0) {
                float sz = zv / (1.f + expf(-zv));
                yp[(size_t)l * DI] = (part + Dd * x_t) * sz;
            }
        }
    }
}

// ---------------------------------------------------------------------------
extern "C" void kernel_launch(void* const* d_in, const int* in_sizes, int n_in,
                              void* d_out, int out_size)
{
    const float* x      = (const float*)d_in[0];
    const float* gamma  = (const float*)d_in[1];
    const float* beta   = (const float*)d_in[2];
    const float* W_in   = (const float*)d_in[3];
    const float* conv_w = (const float*)d_in[4];
    const float* conv_b = (const float*)d_in[5];
    const float* W_xproj= (const float*)d_in[6];
    const float* W_dt   = (const float*)d_in[7];
    const float* b_dt   = (const float*)d_in[8];
    const float* A_log  = (const float*)d_in[9];
    const float* Dw     = (const float*)d_in[10];
    const float* W_out  = (const float*)d_in[11];
    float* out = (float*)d_out;

    static float *hn = nullptr, *xz = nullptr, *xssm = nullptr, *xdbl_part = nullptr,
                 *dtb = nullptr, *yb = nullptr, *xdbl = nullptr;
    if (!hn) {
        cudaGetSymbolAddress((void**)&hn,        g_hn);
        cudaGetSymbolAddress((void**)&xz,        g_xz);
        cudaGetSymbolAddress((void**)&xssm,      g_xssm);
        cudaGetSymbolAddress((void**)&xdbl,      g_xdbl);
        cudaGetSymbolAddress((void**)&xdbl_part, g_xdbl_part);
        cudaGetSymbolAddress((void**)&dtb,       g_dt);
        cudaGetSymbolAddress((void**)&yb,        g_y);
        cudaFuncSetAttribute(gemm_tf32<128, 2, 2, 0>,
                             cudaFuncAttributeMaxDynamicSharedMemorySize, GSMEM(128));
        cudaFuncSetAttribute(gemm_tf32<128, 2, 2, 1>,
                             cudaFuncAttributeMaxDynamicSharedMemorySize, GSMEM(128));
        cudaFuncSetAttribute(gemm_tf32<128, 2, 2, 2>,
                             cudaFuncAttributeMaxDynamicSharedMemorySize, GSMEM(128));
        cudaFuncSetAttribute(gemm_tf32<80, 4, 1, 0>,
                             cudaFuncAttributeMaxDynamicSharedMemorySize, GSMEM(80));
    }

    // 0) profiler alignment dummy (keeps GEMM1 at profiled launch index 3)
    profile_align_kernel<<<1, 32>>>();
    // 1) LN stats
    ln_stats_kernel<<<dim3(Lsz / 64, Bsz), 256>>>(x);
    // 2) transpose + LN apply
    ln_apply_kernel<<<dim3(Lsz / 32, DM / 32, Bsz), dim3(32, 8)>>>(x, gamma, beta);
    // 3) GEMM1: xz = hn @ W_in^T   (4096 x 3072 x 768)
    gemm_tf32<128, 2, 2, 0><<<dim3(3072 / 128, MROWS / 128), 128, GSMEM(128)>>>(
        hn, DM, W_in, DM, xz, 2 * DI, DM, nullptr, nullptr, 0);
    // 4) conv + silu
    conv_silu_kernel<<<(MROWS * DI + 255) / 256, 256>>>(conv_w, conv_b);
    // 5) xproj split-K x6: xdbl_part[z] = xssm @ W_xproj^T over K chunk z
    gemm_tf32<80, 4, 1, 0><<<dim3(1, MROWS / 128, SPLITK), 128, GSMEM(80)>>>(
        xssm, DI, W_xproj, DI, xdbl_part, 80, XPK, nullptr, nullptr, MROWS * 80);
    //    reduce partials -> xdbl
    xdbl_reduce_kernel<<<(MROWS * 80 + 255) / 256, 256>>>();
    // 6) dt = softplus(xdbl[:, :48] @ W_dt^T + b_dt)   (4096 x 1536 x 48)
    gemm_tf32<128, 2, 2, 1><<<dim3(DI / 128, MROWS / 128), 128, GSMEM(128)>>>(
        xdbl, 80, W_dt, DTR, dtb, DI, DTR, b_dt, nullptr, 0);
    // 7) scan (software-pipelined)
    scan_kernel<<<(Bsz * DI * 4 + 127) / 128, 128>>>(A_log, Dw);
    // 8) out = y @ W_out^T, transposed store + residual x   (4096 x 768 x 1536)
    gemm_tf32<128, 2, 2, 2><<<dim3(DM / 128, MROWS / 128), 128, GSMEM(128)>>>(
        yb, DI, W_out, DI, out, 0, DI, nullptr, x, 0);
}

// round 12
// speedup vs baseline: 3.9975x; 1.2087x over previous
#include <cuda_runtime.h>
#include <cuda_bf16.h>
#include <cstdint>

// ---------------------------------------------------------------------------
// MambaBlock: B=4, L=1024, D_MODEL=768, D_INNER=1536, D_STATE=16, DT_RANK=48
// Big GEMMs: mma.sync.m16n8k16.bf16 (2x FLOP/instr vs tf32 - the legacy
// tensor path is instruction-rate-bound).  Small GEMMs: tf32.
// Scan: depth-4 SW pipeline.  xproj: split-K x6 + reduce.
// (Resubmission of R11 - previous run died to an infra flake, per R1/R2
// precedent the identical source is re-benched for clean attribution.)
// ---------------------------------------------------------------------------

#define Bsz 4
#define Lsz 1024
#define DM  768
#define DI  1536
#define DS  16
#define DTR 48
#define MROWS (Bsz * Lsz)   // 4096
#define SPLITK 6
#define XPK (DI / SPLITK)   // 256

__device__ __align__(16) __nv_bfloat16 g_hn_bf [MROWS * DM];
__device__ __align__(16) __nv_bfloat16 g_Win_bf[2 * DI * DM];
__device__ __align__(16) __nv_bfloat16 g_Wout_bf[DM * DI];
__device__ __align__(16) __nv_bfloat16 g_y_bf  [MROWS * DI];
__device__ __align__(16) float g_xz  [MROWS * 2 * DI];
__device__ __align__(16) float g_xssm[MROWS * DI];
__device__ __align__(16) float g_xdbl[MROWS * 80];
__device__ __align__(16) float g_xdbl_part[SPLITK * MROWS * 80];
__device__ __align__(16) float g_dt  [MROWS * DI];
__device__ __align__(16) float g_stats[MROWS * 2];

// ---------------------------------------------------------------------------
// fp32 -> bf16 conversion (weights)
// ---------------------------------------------------------------------------
__global__ void cvt_bf16_kernel(const float* __restrict__ src,
                                __nv_bfloat16* __restrict__ dst, int n)
{
    int i = blockIdx.x * blockDim.x + threadIdx.x;
    if (i < n) dst[i] = __float2bfloat16_rn(src[i]);
}

// ---------------------------------------------------------------------------
// 1) LayerNorm statistics
// ---------------------------------------------------------------------------
__global__ void ln_stats_kernel(const float* __restrict__ x)
{
    __shared__ float s_sum[256];
    __shared__ float s_sq[256];
    int tid  = threadIdx.x;
    int lid  = tid & 63;
    int part = tid >> 6;
    int b    = blockIdx.y;
    int l    = blockIdx.x * 64 + lid;
    const float* xb = x + (size_t)b * DM * Lsz + l;

    float sum = 0.f, sq = 0.f;
    int c0 = part * (DM / 4);
    #pragma unroll 8
    for (int c = c0; c < c0 + DM / 4; c++) {
        float v = xb[(size_t)c * Lsz];
        sum += v;
        sq  += v * v;
    }
    s_sum[tid] = sum;
    s_sq[tid]  = sq;
    __syncthreads();
    if (part == 0) {
        float ts = s_sum[tid] + s_sum[tid + 64] + s_sum[tid + 128] + s_sum[tid + 192];
        float tq = s_sq[tid]  + s_sq[tid + 64]  + s_sq[tid + 128]  + s_sq[tid + 192];
        float mu = ts / DM;
        float var = tq / DM - mu * mu;
        float rstd = rsqrtf(var + 1e-5f);
        int bl = b * Lsz + l;
        g_stats[bl * 2 + 0] = mu;
        g_stats[bl * 2 + 1] = rstd;
    }
}

// ---------------------------------------------------------------------------
// 2) Transpose (B,C,L)->(B*L,C) with LN applied; bf16 output.
// ---------------------------------------------------------------------------
__global__ void ln_apply_kernel(const float* __restrict__ x,
                                const float* __restrict__ gamma,
                                const float* __restrict__ beta)
{
    __shared__ float tile[32][33];
    int b  = blockIdx.z;
    int c0 = blockIdx.y * 32;
    int l0 = blockIdx.x * 32;
    const float* xb = x + (size_t)b * DM * Lsz;

    #pragma unroll
    for (int i0 = 0; i0 < 4; i0++) {
        int c = c0 + threadIdx.y + i0 * 8;
        tile[threadIdx.y + i0 * 8][threadIdx.x] = xb[(size_t)c * Lsz + l0 + threadIdx.x];
    }
    __syncthreads();
    #pragma unroll
    for (int i0 = 0; i0 < 4; i0++) {
        int l  = l0 + threadIdx.y + i0 * 8;
        int c  = c0 + threadIdx.x;
        int bl = b * Lsz + l;
        float mu   = g_stats[bl * 2 + 0];
        float rstd = g_stats[bl * 2 + 1];
        float v = tile[threadIdx.x][threadIdx.y + i0 * 8];
        g_hn_bf[(size_t)bl * DM + c] =
            __float2bfloat16_rn((v - mu) * rstd * gamma[c] + beta[c]);
    }
}

// ---------------------------------------------------------------------------
// mma + cp.async helpers
// ---------------------------------------------------------------------------
__device__ __forceinline__ void mma_tf32(float* c, const uint32_t* a, const uint32_t* b)
{
    asm volatile(
        "mma.sync.aligned.m16n8k8.row.col.f32.tf32.tf32.f32 "
        "{%0,%1,%2,%3}, {%4,%5,%6,%7}, {%8,%9}, {%0,%1,%2,%3};"
        : "+f"(c[0]), "+f"(c[1]), "+f"(c[2]), "+f"(c[3])
        : "r"(a[0]), "r"(a[1]), "r"(a[2]), "r"(a[3]), "r"(b[0]), "r"(b[1]));
}

__device__ __forceinline__ void mma_bf16(float* c, const uint32_t* a, const uint32_t* b)
{
    asm volatile(
        "mma.sync.aligned.m16n8k16.row.col.f32.bf16.bf16.f32 "
        "{%0,%1,%2,%3}, {%4,%5,%6,%7}, {%8,%9}, {%0,%1,%2,%3};"
        : "+f"(c[0]), "+f"(c[1]), "+f"(c[2]), "+f"(c[3])
        : "r"(a[0]), "r"(a[1]), "r"(a[2]), "r"(a[3]), "r"(b[0]), "r"(b[1]));
}

__device__ __forceinline__ void cp16(uint32_t dst_smem, const void* src)
{
    asm volatile("cp.async.cg.shared.global [%0], [%1], 16;"
                 :: "r"(dst_smem), "l"(src));
}
__device__ __forceinline__ void cp_commit()
{
    asm volatile("cp.async.commit_group;");
}
template<int N>
__device__ __forceinline__ void cp_wait()
{
    asm volatile("cp.async.wait_group %0;" :: "n"(N));
}

// ---------------------------------------------------------------------------
// bf16 tensor GEMM:  C[M,N] = A[M,K] * B[N,K]^T  (A,B bf16 row-major, C fp32)
// BM=BN=128, BK=32 (64B/row/stage), 128 threads (2x2 warps, 64x64 tiles),
// 3-stage cp.async.  EPI 0: plain.  EPI 2: transpose store + residual.
// ---------------------------------------------------------------------------
template<int EPI>
__global__ void __launch_bounds__(128, 3)
gemm_bf16(const __nv_bfloat16* __restrict__ A, int lda,
          const __nv_bfloat16* __restrict__ B, int ldb,
          float* __restrict__ C, int ldc,
          int K, const float* __restrict__ xres)
{
    constexpr int NTH = 128;
    constexpr int BM = 128;
    constexpr int MT = 4, NT = 8;       // 64x64 warp tile
    constexpr int LDT = 20;             // words per row (16 data + 4 pad)
    constexpr int ST  = 3;
    constexpr int STG = BM * LDT;       // words per stage per matrix

    extern __shared__ uint32_t smem[];
    uint32_t* Asm = smem;
    uint32_t* Bsm = smem + ST * STG;

    const int tid   = threadIdx.x;
    const int warp  = tid >> 5;
    const int lane  = tid & 31;
    const int g     = lane >> 2;
    const int t     = lane & 3;

    const int wm0 = (warp >> 1) * 64;   // warp_m in {0,1}
    const int wn0 = (warp & 1) * 64;    // warp_n in {0,1}

    const int m0 = blockIdx.y * BM;
    const int n0 = blockIdx.x * BM;

    const int niter = K / 32;

    float acc[MT][NT][4];
    #pragma unroll
    for (int i = 0; i < MT; i++)
        #pragma unroll
        for (int j = 0; j < NT; j++)
            #pragma unroll
            for (int q = 0; q < 4; q++) acc[i][j][q] = 0.f;

    uint32_t sA = (uint32_t)__cvta_generic_to_shared(Asm);
    uint32_t sB = (uint32_t)__cvta_generic_to_shared(Bsm);

    // fill stage s with K-chunk it (32 bf16 = 64B per row = 4 x 16B)
    auto issue = [&](int s, int it) {
        int k0 = it * 32;
        uint32_t baseA = sA + (uint32_t)s * (STG * 4);
        uint32_t baseB = sB + (uint32_t)s * (STG * 4);
        #pragma unroll
        for (int i = 0; i < 512 / NTH; i++) {
            int id = tid + NTH * i;
            int r  = id >> 2;
            int c  = id & 3;
            cp16(baseA + (uint32_t)(r * LDT + c * 4) * 4,
                 &A[(size_t)(m0 + r) * lda + k0 + c * 8]);
            cp16(baseB + (uint32_t)(r * LDT + c * 4) * 4,
                 &B[(size_t)(n0 + r) * ldb + k0 + c * 8]);
        }
    };

    issue(0, 0); cp_commit();
    issue(1, 1); cp_commit();

    for (int it = 0; it < niter; it++) {
        const int s = it % ST;
        cp_wait<1>();
        __syncthreads();

        if (it + 2 < niter) issue((it + 2) % ST, it + 2);
        cp_commit();

        const uint32_t* as = Asm + s * STG;
        const uint32_t* bs = Bsm + s * STG;
        #pragma unroll
        for (int ks = 0; ks < 2; ks++) {
            const int kk = ks * 8;          // word offset of this K=16 slice
            uint32_t afr[MT][4];
            uint32_t bfr[NT][2];
            #pragma unroll
            for (int i = 0; i < MT; i++) {
                int base = wm0 + 16 * i;
                afr[i][0] = as[(base + g)     * LDT + kk + t];
                afr[i][1] = as[(base + g + 8) * LDT + kk + t];
                afr[i][2] = as[(base + g)     * LDT + kk + 4 + t];
                afr[i][3] = as[(base + g + 8) * LDT + kk + 4 + t];
            }
            #pragma unroll
            for (int j = 0; j < NT; j++) {
                int bb = wn0 + 8 * j;
                bfr[j][0] = bs[(bb + g) * LDT + kk + t];
                bfr[j][1] = bs[(bb + g) * LDT + kk + 4 + t];
            }
            #pragma unroll
            for (int i = 0; i < MT; i++)
                #pragma unroll
                for (int j = 0; j < NT; j++)
                    mma_bf16(acc[i][j], afr[i], bfr[j]);
        }
    }

    #pragma unroll
    for (int i = 0; i < MT; i++) {
        int r0 = m0 + wm0 + 16 * i + g;
        int r1 = r0 + 8;
        #pragma unroll
        for (int j = 0; j < NT; j++) {
            int col = n0 + wn0 + 8 * j + 2 * t;
            float c0 = acc[i][j][0], c1 = acc[i][j][1];
            float c2 = acc[i][j][2], c3 = acc[i][j][3];
            if (EPI == 2) {
                int b0i = r0 >> 10, l0i = r0 & 1023;
                int b1i = r1 >> 10, l1i = r1 & 1023;
                size_t o00 = ((size_t)(b0i * DM + col))     * Lsz + l0i;
                size_t o01 = ((size_t)(b0i * DM + col + 1)) * Lsz + l0i;
                size_t o10 = ((size_t)(b1i * DM + col))     * Lsz + l1i;
                size_t o11 = ((size_t)(b1i * DM + col + 1)) * Lsz + l1i;
                C[o00] = c0 + xres[o00];
                C[o01] = c1 + xres[o01];
                C[o10] = c2 + xres[o10];
                C[o11] = c3 + xres[o11];
            } else {
                *reinterpret_cast<float2*>(&C[(size_t)r0 * ldc + col]) = make_float2(c0, c1);
                *reinterpret_cast<float2*>(&C[(size_t)r1 * ldc + col]) = make_float2(c2, c3);
            }
        }
    }
}

// ---------------------------------------------------------------------------
// tf32 tensor GEMM (small GEMMs: xproj split-K, dt).
// ---------------------------------------------------------------------------
template<int BN, int WARPS_M, int WARPS_N, int EPI>
__global__ void __launch_bounds__(32 * WARPS_M * WARPS_N, 3)
gemm_tf32(const float* __restrict__ A, int lda,
          const float* __restrict__ B, int ldb,
          float* __restrict__ C, int ldc,
          int K,
          const float* __restrict__ bias,
          int split_stride)
{
    constexpr int NTH = 32 * WARPS_M * WARPS_N;
    constexpr int BM = 128;
    constexpr int WM = BM / WARPS_M;
    constexpr int WN = BN / WARPS_N;
    constexpr int MT = WM / 16;
    constexpr int NT = WN / 8;
    constexpr int LDT = 20;
    constexpr int NA4 = BM * 4;
    constexpr int NB4 = BN * 4;
    constexpr int ST  = 3;
    constexpr int ASTG = BM * LDT;
    constexpr int BSTG = BN * LDT;

    extern __shared__ uint32_t smem[];
    uint32_t* Asm = smem;
    uint32_t* Bsm = smem + ST * ASTG;

    const int tid   = threadIdx.x;
    const int warp  = tid >> 5;
    const int lane  = tid & 31;
    const int g     = lane >> 2;
    const int t     = lane & 3;

    const int warp_m = warp / WARPS_N;
    const int warp_n = warp % WARPS_N;
    const int wm0 = warp_m * WM;
    const int wn0 = warp_n * WN;

    const int m0 = blockIdx.y * BM;
    const int n0 = blockIdx.x * BN;

    const float* Ae = A + (size_t)blockIdx.z * K;
    const float* Be = B + (size_t)blockIdx.z * K;
    float* Ce = C + (size_t)blockIdx.z * split_stride;

    const int niter = K / 16;

    float acc[MT][NT][4];
    #pragma unroll
    for (int i = 0; i < MT; i++)
        #pragma unroll
        for (int j = 0; j < NT; j++)
            #pragma unroll
            for (int q = 0; q < 4; q++) acc[i][j][q] = 0.f;

    uint32_t sA = (uint32_t)__cvta_generic_to_shared(Asm);
    uint32_t sB = (uint32_t)__cvta_generic_to_shared(Bsm);

    auto issue = [&](int s, int it) {
        int k0 = it * 16;
        uint32_t baseA = sA + (uint32_t)s * (ASTG * 4);
        #pragma unroll
        for (int i = 0; i < NA4 / NTH; i++) {
            int id = tid + NTH * i;
            int r  = id >> 2;
            int kq = (id & 3) * 4;
            cp16(baseA + (uint32_t)(r * LDT + kq) * 4,
                 &Ae[(size_t)(m0 + r) * lda + k0 + kq]);
        }
        uint32_t baseB = sB + (uint32_t)s * (BSTG * 4);
        #pragma unroll
        for (int i = 0; i < (NB4 + NTH - 1) / NTH; i++) {
            int id = tid + NTH * i;
            if (id < NB4) {
                int r  = id >> 2;
                int kq = (id & 3) * 4;
                cp16(baseB + (uint32_t)(r * LDT + kq) * 4,
                     &Be[(size_t)(n0 + r) * ldb + k0 + kq]);
            }
        }
    };

    issue(0, 0); cp_commit();
    issue(1, 1); cp_commit();

    for (int it = 0; it < niter; it++) {
        const int s = it % ST;
        cp_wait<1>();
        __syncthreads();

        if (it + 2 < niter) issue((it + 2) % ST, it + 2);
        cp_commit();

        const uint32_t* as = Asm + s * ASTG;
        const uint32_t* bs = Bsm + s * BSTG;
        #pragma unroll
        for (int ks = 0; ks < 2; ks++) {
            const int kk = ks * 8;
            uint32_t afr[MT][4];
            uint32_t bfr[NT][2];
            #pragma unroll
            for (int i = 0; i < MT; i++) {
                int base = wm0 + 16 * i;
                afr[i][0] = as[(base + g)     * LDT + kk + t];
                afr[i][1] = as[(base + g + 8) * LDT + kk + t];
                afr[i][2] = as[(base + g)     * LDT + kk + t + 4];
                afr[i][3] = as[(base + g + 8) * LDT + kk + t + 4];
            }
            #pragma unroll
            for (int j = 0; j < NT; j++) {
                int bb = wn0 + 8 * j;
                bfr[j][0] = bs[(bb + g) * LDT + kk + t];
                bfr[j][1] = bs[(bb + g) * LDT + kk + t + 4];
            }
            #pragma unroll
            for (int i = 0; i < MT; i++)
                #pragma unroll
                for (int j = 0; j < NT; j++)
                    mma_tf32(acc[i][j], afr[i], bfr[j]);
        }
    }

    #pragma unroll
    for (int i = 0; i < MT; i++) {
        int r0 = m0 + wm0 + 16 * i + g;
        int r1 = r0 + 8;
        #pragma unroll
        for (int j = 0; j < NT; j++) {
            int col = n0 + wn0 + 8 * j + 2 * t;
            float c0 = acc[i][j][0], c1 = acc[i][j][1];
            float c2 = acc[i][j][2], c3 = acc[i][j][3];
            if (EPI == 1) {
                float b0 = bias[col], b1 = bias[col + 1];
                c0 += b0; c1 += b1; c2 += b0; c3 += b1;
                c0 = (c0 > 20.f) ? c0 : log1pf(expf(c0));
                c1 = (c1 > 20.f) ? c1 : log1pf(expf(c1));
                c2 = (c2 > 20.f) ? c2 : log1pf(expf(c2));
                c3 = (c3 > 20.f) ? c3 : log1pf(expf(c3));
            }
            *reinterpret_cast<float2*>(&Ce[(size_t)r0 * ldc + col]) = make_float2(c0, c1);
            *reinterpret_cast<float2*>(&Ce[(size_t)r1 * ldc + col]) = make_float2(c2, c3);
        }
    }
}

#define GSMEM(BN) (3 * (128 + (BN)) * 20 * 4)
#define GSMEM_BF  (3 * 2 * 128 * 20 * 4)

// reduce the SPLITK partial xproj results -> g_xdbl (deterministic order)
__global__ void xdbl_reduce_kernel()
{
    int idx = blockIdx.x * blockDim.x + threadIdx.x;
    if (idx >= MROWS * 80) return;
    float s = 0.f;
    #pragma unroll
    for (int p = 0; p < SPLITK; p++)
        s += g_xdbl_part[(size_t)p * (MROWS * 80) + idx];
    g_xdbl[idx] = s;
}

// ---------------------------------------------------------------------------
// 4) depthwise causal conv(4) + bias + silu
// ---------------------------------------------------------------------------
__global__ void conv_silu_kernel(const float* __restrict__ conv_w,
                                 const float* __restrict__ conv_b)
{
    int idx = blockIdx.x * blockDim.x + threadIdx.x;
    if (idx >= MROWS * DI) return;
    int d  = idx % DI;
    int bl = idx / DI;
    int l  = bl & (Lsz - 1);

    float acc = conv_b[d];
    #pragma unroll
    for (int j = 0; j < 4; j++) {
        int ll = l - 3 + j;
        if (ll >= 0)
            acc += conv_w[d * 4 + j] * g_xz[(size_t)(bl - 3 + j) * (2 * DI) + d];
    }
    g_xssm[idx] = acc / (1.f + expf(-acc));
}

// ---------------------------------------------------------------------------
// 7) selective scan: 4 lanes per (b,d), depth-4 software pipeline; bf16 y out.
// ---------------------------------------------------------------------------
#define PF 4

__global__ void __launch_bounds__(128)
scan_kernel(const float* __restrict__ A_log,
            const float* __restrict__ Dw)
{
    int pair = blockIdx.x * (blockDim.x >> 2) + (threadIdx.x >> 2);
    if (pair >= Bsz * DI) return;
    int ln = threadIdx.x & 3;
    int b = pair / DI;
    int d = pair % DI;
    int n0 = ln * 4;

    float Av[4], h[4];
    #pragma unroll
    for (int j = 0; j < 4; j++) {
        Av[j] = -expf(A_log[d * DS + n0 + j]);
        h[j] = 0.f;
    }
    float Dd = Dw[d];

    const float* dtp = g_dt   + (size_t)b * Lsz * DI + d;
    const float* xp  = g_xssm + (size_t)b * Lsz * DI + d;
    const float* dbl = g_xdbl + (size_t)b * Lsz * 80;
    const float* zp  = g_xz   + (size_t)b * Lsz * (2 * DI) + DI + d;
    __nv_bfloat16* yp = g_y_bf + (size_t)b * Lsz * DI + d;

    float  pdt[PF], px[PF], pz[PF];
    float4 pB[PF], pC[PF];

    #pragma unroll
    for (int j = 0; j < PF; j++) {
        pdt[j] = dtp[(size_t)j * DI];
        px[j]  = xp [(size_t)j * DI];
        pB[j]  = *reinterpret_cast<const float4*>(&dbl[j * 80 + DTR + n0]);
        pC[j]  = *reinterpret_cast<const float4*>(&dbl[j * 80 + DTR + DS + n0]);
        pz[j]  = zp[(size_t)j * (2 * DI)];
    }

    for (int l0 = 0; l0 < Lsz; l0 += PF) {
        #pragma unroll
        for (int j = 0; j < PF; j++) {
            const int l = l0 + j;
            float  dt_t = pdt[j];
            float  x_t  = px[j];
            float4 Bv   = pB[j];
            float4 Cv   = pC[j];
            float  zv   = pz[j];
            const int lf = l + PF;
            if (lf < Lsz) {
                pdt[j] = dtp[(size_t)lf * DI];
                px[j]  = xp [(size_t)lf * DI];
                pB[j]  = *reinterpret_cast<const float4*>(&dbl[lf * 80 + DTR + n0]);
                pC[j]  = *reinterpret_cast<const float4*>(&dbl[lf * 80 + DTR + DS + n0]);
                pz[j]  = zp[(size_t)lf * (2 * DI)];
            }
            float dtx = dt_t * x_t;
            h[0] = expf(dt_t * Av[0]) * h[0] + dtx * Bv.x;
            h[1] = expf(dt_t * Av[1]) * h[1] + dtx * Bv.y;
            h[2] = expf(dt_t * Av[2]) * h[2] + dtx * Bv.z;
            h[3] = expf(dt_t * Av[3]) * h[3] + dtx * Bv.w;
            float part = h[0] * Cv.x + h[1] * Cv.y + h[2] * Cv.z + h[3] * Cv.w;
            part += __shfl_xor_sync(0xFFFFFFFFu, part, 2);
            part += __shfl_xor_sync(0xFFFFFFFFu, part, 1);
            if (ln == 0) {
                float sz = zv / (1.f + expf(-zv));
                yp[(size_t)l * DI] = __float2bfloat16_rn((part + Dd * x_t) * sz);
            }
        }
    }
}

// ---------------------------------------------------------------------------
extern "C" void kernel_launch(void* const* d_in, const int* in_sizes, int n_in,
                              void* d_out, int out_size)
{
    const float* x      = (const float*)d_in[0];
    const float* gamma  = (const float*)d_in[1];
    const float* beta   = (const float*)d_in[2];
    const float* W_in   = (const float*)d_in[3];
    const float* conv_w = (const float*)d_in[4];
    const float* conv_b = (const float*)d_in[5];
    const float* W_xproj= (const float*)d_in[6];
    const float* W_dt   = (const float*)d_in[7];
    const float* b_dt   = (const float*)d_in[8];
    const float* A_log  = (const float*)d_in[9];
    const float* Dw     = (const float*)d_in[10];
    const float* W_out  = (const float*)d_in[11];
    float* out = (float*)d_out;

    static float *xz = nullptr, *xssm = nullptr, *xdbl = nullptr,
                 *xdbl_part = nullptr, *dtb = nullptr;
    static __nv_bfloat16 *hn_bf = nullptr, *Win_bf = nullptr,
                         *Wout_bf = nullptr, *y_bf = nullptr;
    if (!xz) {
        cudaGetSymbolAddress((void**)&xz,        g_xz);
        cudaGetSymbolAddress((void**)&xssm,      g_xssm);
        cudaGetSymbolAddress((void**)&xdbl,      g_xdbl);
        cudaGetSymbolAddress((void**)&xdbl_part, g_xdbl_part);
        cudaGetSymbolAddress((void**)&dtb,       g_dt);
        cudaGetSymbolAddress((void**)&hn_bf,     g_hn_bf);
        cudaGetSymbolAddress((void**)&Win_bf,    g_Win_bf);
        cudaGetSymbolAddress((void**)&Wout_bf,   g_Wout_bf);
        cudaGetSymbolAddress((void**)&y_bf,      g_y_bf);
        cudaFuncSetAttribute(gemm_bf16<0>,
                             cudaFuncAttributeMaxDynamicSharedMemorySize, GSMEM_BF);
        cudaFuncSetAttribute(gemm_bf16<2>,
                             cudaFuncAttributeMaxDynamicSharedMemorySize, GSMEM_BF);
        cudaFuncSetAttribute(gemm_tf32<128, 2, 2, 1>,
                             cudaFuncAttributeMaxDynamicSharedMemorySize, GSMEM(128));
        cudaFuncSetAttribute(gemm_tf32<80, 4, 1, 0>,
                             cudaFuncAttributeMaxDynamicSharedMemorySize, GSMEM(80));
    }

    // 0) convert W_in to bf16 (keeps GEMM1 at profiled launch index 3)
    cvt_bf16_kernel<<<(2 * DI * DM + 255) / 256, 256>>>(W_in, Win_bf, 2 * DI * DM);
    // 1) LN stats
    ln_stats_kernel<<<dim3(Lsz / 64, Bsz), 256>>>(x);
    // 2) transpose + LN apply (bf16 out)
    ln_apply_kernel<<<dim3(Lsz / 32, DM / 32, Bsz), dim3(32, 8)>>>(x, gamma, beta);
    // 3) GEMM1 (bf16): xz = hn @ W_in^T   (4096 x 3072 x 768)
    gemm_bf16<0><<<dim3(3072 / 128, MROWS / 128), 128, GSMEM_BF>>>(
        hn_bf, DM, Win_bf, DM, xz, 2 * DI, DM, nullptr);
    // 4) conv + silu
    conv_silu_kernel<<<(MROWS * DI + 255) / 256, 256>>>(conv_w, conv_b);
    // 5) xproj split-K x6 + reduce
    gemm_tf32<80, 4, 1, 0><<<dim3(1, MROWS / 128, SPLITK), 128, GSMEM(80)>>>(
        xssm, DI, W_xproj, DI, xdbl_part, 80, XPK, nullptr, MROWS * 80);
    xdbl_reduce_kernel<<<(MROWS * 80 + 255) / 256, 256>>>();
    // 6) dt = softplus(xdbl[:, :48] @ W_dt^T + b_dt)
    gemm_tf32<128, 2, 2, 1><<<dim3(DI / 128, MROWS / 128), 128, GSMEM(128)>>>(
        xdbl, 80, W_dt, DTR, dtb, DI, DTR, b_dt, 0);
    // 6.5) convert W_out to bf16
    cvt_bf16_kernel<<<(DM * DI + 255) / 256, 256>>>(W_out, Wout_bf, DM * DI);
    // 7) scan (bf16 y out)
    scan_kernel<<<(Bsz * DI * 4 + 127) / 128, 128>>>(A_log, Dw);
    // 8) GEMM out (bf16): out = y @ W_out^T, transpose + residual
    gemm_bf16<2><<<dim3(DM / 128, MROWS / 128), 128, GSMEM_BF>>>(
        y_bf, DI, Wout_bf, DI, out, 0, DI, x);
}